// round 1
// baseline (speedup 1.0000x reference)
#include <cuda_runtime.h>
#include <cuda_bf16.h>
#include <math.h>

// Problem constants
#define Cdim 384
#define NHh  4
#define HDd  96
#define Hh   64
#define Ww   128
#define Bb   8
#define HWs  8192                 // H*W
#define NTOK 65536                // B*H*W
#define NELEM 25165824            // B*C*H*W
#define EPSI 1e-5f

// ---------------- scratch (device globals; allocation-free) ----------------
__device__ float g_Q[NELEM];
__device__ float g_K[NELEM];
__device__ float g_V[NELEM];
__device__ float g_A[NELEM];   // attention output (pre-wo)
__device__ float g_O[NELEM];   // after wo projection
__device__ float g_F[NELEM];   // fused (pre-BN)
__device__ float g_scale[Cdim];
__device__ float g_shift[Cdim];

// ---------------- generic 1x1-conv GEMM: Out[m,t] = sum_k W[m,k]*X[k,t] + b[m] ----
// X layout: [B, Kdim, H, W]; Out layout: [B, 384, H, W].
// Tile: BM=128 x BN=128 x BK=16, 256 threads, 8x8 register micro-tile.
__global__ __launch_bounds__(256) void gemm_bias_kernel(
    const float* __restrict__ Wm, const float* __restrict__ X,
    const float* __restrict__ bias, float* __restrict__ Out, int Kdim)
{
    __shared__ float As[16][132];   // [k][m], padded
    __shared__ float Bs[16][128];   // [k][t]

    const int tid = threadIdx.x;
    const int bx = blockIdx.x, by = blockIdx.y;
    const int bIdx = bx >> 6;             // 64 token-tiles per batch image
    const int s0   = (bx & 63) << 7;      // spatial offset within batch
    const int m0   = by << 7;

    const float* Xb = X + (size_t)bIdx * Kdim * HWs + s0;
    float*       Ob = Out + (size_t)bIdx * Cdim * HWs + s0;

    const int ty = tid >> 4, tx = tid & 15;
    const int ar_m = tid >> 2;            // 0..63
    const int ar_k = (tid & 3) << 2;      // 0,4,8,12
    const int br_r = tid >> 5;            // 0..7
    const int br_c = (tid & 31) << 2;     // 0..124

    float acc[8][8];
#pragma unroll
    for (int i = 0; i < 8; i++)
#pragma unroll
        for (int j = 0; j < 8; j++) acc[i][j] = 0.f;

    for (int k0 = 0; k0 < Kdim; k0 += 16) {
#pragma unroll
        for (int r = 0; r < 2; r++) {
            int m = ar_m + r * 64;
            float4 wv = *(const float4*)(Wm + (size_t)(m0 + m) * Kdim + k0 + ar_k);
            As[ar_k + 0][m] = wv.x; As[ar_k + 1][m] = wv.y;
            As[ar_k + 2][m] = wv.z; As[ar_k + 3][m] = wv.w;
        }
#pragma unroll
        for (int r = 0; r < 2; r++) {
            int row = br_r + r * 8;
            *(float4*)(&Bs[row][br_c]) =
                *(const float4*)(Xb + (size_t)(k0 + row) * HWs + br_c);
        }
        __syncthreads();
#pragma unroll
        for (int kk = 0; kk < 16; kk++) {
            float4 a0 = *(const float4*)(&As[kk][ty * 8]);
            float4 a1 = *(const float4*)(&As[kk][ty * 8 + 4]);
            float4 b0 = *(const float4*)(&Bs[kk][tx * 8]);
            float4 b1 = *(const float4*)(&Bs[kk][tx * 8 + 4]);
            float a[8] = {a0.x, a0.y, a0.z, a0.w, a1.x, a1.y, a1.z, a1.w};
            float b[8] = {b0.x, b0.y, b0.z, b0.w, b1.x, b1.y, b1.z, b1.w};
#pragma unroll
            for (int i = 0; i < 8; i++)
#pragma unroll
                for (int j = 0; j < 8; j++) acc[i][j] += a[i] * b[j];
        }
        __syncthreads();
    }
#pragma unroll
    for (int i = 0; i < 8; i++) {
        int m = m0 + ty * 8 + i;
        float bv = bias[m];
        float4 o0 = make_float4(acc[i][0] + bv, acc[i][1] + bv, acc[i][2] + bv, acc[i][3] + bv);
        float4 o1 = make_float4(acc[i][4] + bv, acc[i][5] + bv, acc[i][6] + bv, acc[i][7] + bv);
        *(float4*)(Ob + (size_t)m * HWs + tx * 8)     = o0;
        *(float4*)(Ob + (size_t)m * HWs + tx * 8 + 4) = o1;
    }
}

// ---------------- gate GEMM (K=768, concat input) + fused sigmoid-gate epilogue ----
__global__ __launch_bounds__(256) void gemm_gate_kernel(
    const float* __restrict__ Wg, const float* __restrict__ FS,
    const float* __restrict__ OP, const float* __restrict__ bias,
    float* __restrict__ Fused)
{
    __shared__ float As[16][132];
    __shared__ float Bs[16][128];

    const int tid = threadIdx.x;
    const int bx = blockIdx.x, by = blockIdx.y;
    const int bIdx = bx >> 6;
    const int s0   = (bx & 63) << 7;
    const int m0   = by << 7;

    const float* FSb = FS + (size_t)bIdx * Cdim * HWs + s0;
    const float* OPb = OP + (size_t)bIdx * Cdim * HWs + s0;
    float*       Fb  = Fused + (size_t)bIdx * Cdim * HWs + s0;

    const int ty = tid >> 4, tx = tid & 15;
    const int ar_m = tid >> 2;
    const int ar_k = (tid & 3) << 2;
    const int br_r = tid >> 5;
    const int br_c = (tid & 31) << 2;

    float acc[8][8];
#pragma unroll
    for (int i = 0; i < 8; i++)
#pragma unroll
        for (int j = 0; j < 8; j++) acc[i][j] = 0.f;

    for (int k0 = 0; k0 < 768; k0 += 16) {
#pragma unroll
        for (int r = 0; r < 2; r++) {
            int m = ar_m + r * 64;
            float4 wv = *(const float4*)(Wg + (size_t)(m0 + m) * 768 + k0 + ar_k);
            As[ar_k + 0][m] = wv.x; As[ar_k + 1][m] = wv.y;
            As[ar_k + 2][m] = wv.z; As[ar_k + 3][m] = wv.w;
        }
#pragma unroll
        for (int r = 0; r < 2; r++) {
            int row = br_r + r * 8;
            int kg  = k0 + row;
            const float* src = (kg < 384)
                ? (FSb + (size_t)kg * HWs)
                : (OPb + (size_t)(kg - 384) * HWs);
            *(float4*)(&Bs[row][br_c]) = *(const float4*)(src + br_c);
        }
        __syncthreads();
#pragma unroll
        for (int kk = 0; kk < 16; kk++) {
            float4 a0 = *(const float4*)(&As[kk][ty * 8]);
            float4 a1 = *(const float4*)(&As[kk][ty * 8 + 4]);
            float4 b0 = *(const float4*)(&Bs[kk][tx * 8]);
            float4 b1 = *(const float4*)(&Bs[kk][tx * 8 + 4]);
            float a[8] = {a0.x, a0.y, a0.z, a0.w, a1.x, a1.y, a1.z, a1.w};
            float b[8] = {b0.x, b0.y, b0.z, b0.w, b1.x, b1.y, b1.z, b1.w};
#pragma unroll
            for (int i = 0; i < 8; i++)
#pragma unroll
                for (int j = 0; j < 8; j++) acc[i][j] += a[i] * b[j];
        }
        __syncthreads();
    }
#pragma unroll
    for (int i = 0; i < 8; i++) {
        int m = m0 + ty * 8 + i;
        float bv = bias[m];
        const float* fsr = FSb + (size_t)m * HWs + tx * 8;
        const float* opr = OPb + (size_t)m * HWs + tx * 8;
        float4 f0 = *(const float4*)(fsr);
        float4 f1 = *(const float4*)(fsr + 4);
        float4 p0 = *(const float4*)(opr);
        float4 p1 = *(const float4*)(opr + 4);
        float g[8];
#pragma unroll
        for (int j = 0; j < 8; j++) g[j] = 1.f / (1.f + __expf(-(acc[i][j] + bv)));
        float4 r0 = make_float4(f0.x + g[0]*p0.x, f0.y + g[1]*p0.y,
                                f0.z + g[2]*p0.z, f0.w + g[3]*p0.w);
        float4 r1 = make_float4(f1.x + g[4]*p1.x, f1.y + g[5]*p1.y,
                                f1.z + g[6]*p1.z, f1.w + g[7]*p1.w);
        *(float4*)(Fb + (size_t)m * HWs + tx * 8)     = r0;
        *(float4*)(Fb + (size_t)m * HWs + tx * 8 + 4) = r1;
    }
}

// ---------------- per-row epipolar attention: one CTA per (b,n,h) --------------
// S = (Q^T K)/sqrt(HD) over channels, softmax over v, O = V P^T.
#define VPAD 100
#define SPAD 132
__global__ __launch_bounds__(256) void attn_kernel(
    const float* __restrict__ Q, const float* __restrict__ K,
    const float* __restrict__ V, float* __restrict__ O)
{
    extern __shared__ float sm[];
    float* Qs = sm;                          // [96][128]
    float* Ks = Qs + HDd * Ww;               // [96][128]
    float* Vt = Ks + HDd * Ww;               // [128][VPAD] (transposed V)
    float* Ss = Vt + Ww * VPAD;              // [128][SPAD]

    const int g = blockIdx.x;
    const int h = g & 63;
    const int n = (g >> 6) & 3;
    const int b = g >> 8;
    const size_t base = ((size_t)b * Cdim + (size_t)n * HDd) * HWs + (size_t)h * Ww;
    const int tid = threadIdx.x;

    for (int i = tid; i < HDd * Ww; i += 256) {
        int c = i >> 7, w = i & 127;
        size_t a = base + (size_t)c * HWs + w;
        Qs[i] = Q[a];
        Ks[i] = K[a];
        Vt[w * VPAD + c] = V[a];
    }
    __syncthreads();

    // scores: thread = (w, half of v-range)
    const int w  = tid >> 1;
    const int vb = (tid & 1) << 6;
    float acc[64];
#pragma unroll
    for (int i = 0; i < 64; i++) acc[i] = 0.f;
    for (int c = 0; c < HDd; c++) {
        float qv = Qs[c * Ww + w];
        const float4* kr = (const float4*)(Ks + c * Ww + vb);
#pragma unroll
        for (int j = 0; j < 16; j++) {
            float4 kv = kr[j];
            acc[4*j+0] += qv * kv.x; acc[4*j+1] += qv * kv.y;
            acc[4*j+2] += qv * kv.z; acc[4*j+3] += qv * kv.w;
        }
    }
    const float sc = 0.10206207261596575f;   // 1/sqrt(96)
    float4* srow = (float4*)(Ss + w * SPAD + vb);
#pragma unroll
    for (int j = 0; j < 16; j++)
        srow[j] = make_float4(acc[4*j+0]*sc, acc[4*j+1]*sc, acc[4*j+2]*sc, acc[4*j+3]*sc);
    __syncthreads();

    // softmax per row
    if (tid < Ww) {
        float* r = Ss + tid * SPAD;
        float m = r[0];
#pragma unroll 4
        for (int v = 1; v < Ww; v++) m = fmaxf(m, r[v]);
        float s = 0.f;
#pragma unroll 4
        for (int v = 0; v < Ww; v++) { float e = __expf(r[v] - m); r[v] = e; s += e; }
        float inv = 1.f / s;
#pragma unroll 4
        for (int v = 0; v < Ww; v++) r[v] *= inv;
    }
    __syncthreads();

    // O[c][w] = sum_v Vt[v][c] * P[w][v] ; thread = (w, half of c-range)
    const int cb = (tid & 1) * 48;
    float oacc[48];
#pragma unroll
    for (int i = 0; i < 48; i++) oacc[i] = 0.f;
    const float* prow = Ss + w * SPAD;
    for (int v = 0; v < Ww; v++) {
        float p = prow[v];
        const float4* vr = (const float4*)(Vt + v * VPAD + cb);
#pragma unroll
        for (int j = 0; j < 12; j++) {
            float4 vv = vr[j];
            oacc[4*j+0] += p * vv.x; oacc[4*j+1] += p * vv.y;
            oacc[4*j+2] += p * vv.z; oacc[4*j+3] += p * vv.w;
        }
    }
#pragma unroll
    for (int j = 0; j < 48; j++)
        O[base + (size_t)(cb + j) * HWs + w] = oacc[j];
}

// ---------------- BatchNorm: stats then apply --------------------------------
__global__ __launch_bounds__(256) void bn_stats_kernel(
    const float* __restrict__ F, const float* __restrict__ gamma,
    const float* __restrict__ beta, float* __restrict__ scale,
    float* __restrict__ shift)
{
    const int c = blockIdx.x;
    const int tid = threadIdx.x;
    float s = 0.f, s2 = 0.f;
    for (int i = tid; i < Bb * HWs; i += 256) {
        int b = i >> 13, sp = i & 8191;
        float v = F[(size_t)b * Cdim * HWs + (size_t)c * HWs + sp];
        s += v; s2 += v * v;
    }
    __shared__ float rs[256], rs2[256];
    rs[tid] = s; rs2[tid] = s2;
    __syncthreads();
    for (int o = 128; o > 0; o >>= 1) {
        if (tid < o) { rs[tid] += rs[tid + o]; rs2[tid] += rs2[tid + o]; }
        __syncthreads();
    }
    if (tid == 0) {
        float mean = rs[0] * (1.f / 65536.f);
        float var  = rs2[0] * (1.f / 65536.f) - mean * mean;
        float sv = gamma[c] * rsqrtf(var + EPSI);
        scale[c] = sv;
        shift[c] = beta[c] - mean * sv;
    }
}

__global__ __launch_bounds__(256) void bn_apply_kernel(
    const float* __restrict__ F, const float* __restrict__ scale,
    const float* __restrict__ shift, float* __restrict__ Out)
{
    int idx = blockIdx.x * blockDim.x + threadIdx.x;   // float4 index
    if (idx >= NELEM / 4) return;
    int c = (idx >> 11) % Cdim;
    float sv = scale[c], sh = shift[c];
    float4 v = ((const float4*)F)[idx];
    float4 o = make_float4(v.x * sv + sh, v.y * sv + sh, v.z * sv + sh, v.w * sv + sh);
    ((float4*)Out)[idx] = o;
}

// ---------------- launch ------------------------------------------------------
extern "C" void kernel_launch(void* const* d_in, const int* in_sizes, int n_in,
                              void* d_out, int out_size)
{
    const float* fs    = (const float*)d_in[0];
    const float* fo    = (const float*)d_in[1];
    const float* wq    = (const float*)d_in[2];
    const float* bq    = (const float*)d_in[3];
    const float* wk    = (const float*)d_in[4];
    const float* bk    = (const float*)d_in[5];
    const float* wv    = (const float*)d_in[6];
    const float* bv    = (const float*)d_in[7];
    const float* wo    = (const float*)d_in[8];
    const float* bo    = (const float*)d_in[9];
    const float* wg    = (const float*)d_in[10];
    const float* bg    = (const float*)d_in[11];
    const float* gamma = (const float*)d_in[12];
    const float* beta  = (const float*)d_in[13];
    float* out = (float*)d_out;

    float *pQ, *pK, *pV, *pA, *pO, *pF, *pScale, *pShift;
    cudaGetSymbolAddress((void**)&pQ, g_Q);
    cudaGetSymbolAddress((void**)&pK, g_K);
    cudaGetSymbolAddress((void**)&pV, g_V);
    cudaGetSymbolAddress((void**)&pA, g_A);
    cudaGetSymbolAddress((void**)&pO, g_O);
    cudaGetSymbolAddress((void**)&pF, g_F);
    cudaGetSymbolAddress((void**)&pScale, g_scale);
    cudaGetSymbolAddress((void**)&pShift, g_shift);

    const int smem_attn = (HDd * Ww * 2 + Ww * VPAD + Ww * SPAD) * sizeof(float); // 217088
    cudaFuncSetAttribute(attn_kernel, cudaFuncAttributeMaxDynamicSharedMemorySize, smem_attn);

    dim3 ggrid(512, 3);
    gemm_bias_kernel<<<ggrid, 256>>>(wq, fs, bq, pQ, Cdim);
    gemm_bias_kernel<<<ggrid, 256>>>(wk, fo, bk, pK, Cdim);
    gemm_bias_kernel<<<ggrid, 256>>>(wv, fo, bv, pV, Cdim);

    attn_kernel<<<Bb * NHh * Hh, 256, smem_attn>>>(pQ, pK, pV, pA);

    gemm_bias_kernel<<<ggrid, 256>>>(wo, pA, bo, pO, Cdim);
    gemm_gate_kernel<<<ggrid, 256>>>(wg, fs, pO, bg, pF);

    bn_stats_kernel<<<Cdim, 256>>>(pF, gamma, beta, pScale, pShift);
    bn_apply_kernel<<<NELEM / 4 / 256, 256>>>(pF, pScale, pShift, out);
}

// round 12
// speedup vs baseline: 1.0583x; 1.0583x over previous
#include <cuda_runtime.h>
#include <cuda_bf16.h>
#include <math.h>
#include <cstdint>

// Problem constants
#define Cdim 384
#define NHh  4
#define HDd  96
#define Hh   64
#define Ww   128
#define Bb   8
#define HWs  8192                 // H*W
#define NELEM 25165824            // B*C*H*W
#define EPSI 1e-5f

// ---------------- scratch (device globals; allocation-free) ----------------
__device__ float g_Q[NELEM];
__device__ float g_K[NELEM];
__device__ float g_V[NELEM];
__device__ float g_A[NELEM];   // attention output (pre-wo)
__device__ float g_O[NELEM];   // after wo projection
__device__ float g_F[NELEM];   // fused (pre-BN)
__device__ float g_scale[Cdim];
__device__ float g_shift[Cdim];

// ---------------- tf32 helpers ----------------------------------------------
__device__ __forceinline__ float to_tf32(float x) {
    uint32_t u;
    asm("cvt.rna.tf32.f32 %0, %1;" : "=r"(u) : "f"(x));
    return __uint_as_float(u);
}

__device__ __forceinline__ void mma_tf32(
    float& c0, float& c1, float& c2, float& c3,
    uint32_t a0, uint32_t a1, uint32_t a2, uint32_t a3,
    uint32_t b0, uint32_t b1)
{
    asm volatile(
        "mma.sync.aligned.m16n8k8.row.col.f32.tf32.tf32.f32 "
        "{%0,%1,%2,%3}, {%4,%5,%6,%7}, {%8,%9}, {%0,%1,%2,%3};"
        : "+f"(c0), "+f"(c1), "+f"(c2), "+f"(c3)
        : "r"(a0), "r"(a1), "r"(a2), "r"(a3), "r"(b0), "r"(b1));
}

// smem geometry (floats)
#define ALD 36          // A tile lds: bank = 4*g + tg, conflict-free
#define BLD 136         // B tile lds: bank = 8*tg + g, conflict-free
#define OFF_AH 0
#define OFF_AL (128 * ALD)            // 4608
#define OFF_BH (2 * 128 * ALD)        // 9216
#define OFF_BL (2 * 128 * ALD + 32 * BLD)  // 13568
#define SMEM_FLOATS (2 * 128 * ALD + 2 * 32 * BLD)  // 17920 -> 71680 B

// ---------------- split-tf32 GEMM core (shared by both kernels) --------------
// Computes acc[2][8][4] for this warp over one 128x128x(Kdim) tile.
// A = W[m,k] row-major (stride Kdim); B = X[k,t] (stride HWs).
struct GemmCore {
    float acc[2][8][4];
};

__device__ __forceinline__ void load_a_tile(
    float* sm, const float* __restrict__ Wm, int m0, int Kdim, int k0, int tid)
{
    const int arow = tid >> 1;
    const int akc  = (tid & 1) << 4;
    const float* wrow = Wm + (size_t)(m0 + arow) * Kdim + k0 + akc;
    float* ah = sm + OFF_AH + arow * ALD + akc;
    float* al = sm + OFF_AL + arow * ALD + akc;
#pragma unroll
    for (int u = 0; u < 4; u++) {
        float4 v = *(const float4*)(wrow + u * 4);
        float h0 = to_tf32(v.x), h1 = to_tf32(v.y), h2 = to_tf32(v.z), h3 = to_tf32(v.w);
        *(float4*)(ah + u * 4) = make_float4(h0, h1, h2, h3);
        *(float4*)(al + u * 4) = make_float4(
            to_tf32(v.x - h0), to_tf32(v.y - h1), to_tf32(v.z - h2), to_tf32(v.w - h3));
    }
}

__device__ __forceinline__ void load_b_row(
    float* sm, const float* __restrict__ xrow, int bkr, int btc)
{
    float* bh = sm + OFF_BH + bkr * BLD + btc;
    float* bl = sm + OFF_BL + bkr * BLD + btc;
#pragma unroll
    for (int u = 0; u < 4; u++) {
        float4 v = *(const float4*)(xrow + u * 4);
        float h0 = to_tf32(v.x), h1 = to_tf32(v.y), h2 = to_tf32(v.z), h3 = to_tf32(v.w);
        *(float4*)(bh + u * 4) = make_float4(h0, h1, h2, h3);
        *(float4*)(bl + u * 4) = make_float4(
            to_tf32(v.x - h0), to_tf32(v.y - h1), to_tf32(v.z - h2), to_tf32(v.w - h3));
    }
}

__device__ __forceinline__ void mma_chunk(
    const float* sm, GemmCore& gc, int wm, int wt, int g, int tg)
{
#pragma unroll
    for (int ks = 0; ks < 4; ks++) {
        const int kb = ks << 3;
        uint32_t ah[2][4], al[2][4];
#pragma unroll
        for (int im = 0; im < 2; im++) {
            const float* bh_ = sm + OFF_AH + (wm + (im << 4) + g) * ALD + kb;
            const float* bl_ = sm + OFF_AL + (wm + (im << 4) + g) * ALD + kb;
            ah[im][0] = __float_as_uint(bh_[tg]);
            ah[im][1] = __float_as_uint(bh_[8 * ALD + tg]);
            ah[im][2] = __float_as_uint(bh_[tg + 4]);
            ah[im][3] = __float_as_uint(bh_[8 * ALD + tg + 4]);
            al[im][0] = __float_as_uint(bl_[tg]);
            al[im][1] = __float_as_uint(bl_[8 * ALD + tg]);
            al[im][2] = __float_as_uint(bl_[tg + 4]);
            al[im][3] = __float_as_uint(bl_[tg + 4 + 8 * ALD]);
        }
#pragma unroll
        for (int jf = 0; jf < 8; jf++) {
            const int tl = wt + (jf << 3) + g;
            uint32_t bh0 = __float_as_uint(sm[OFF_BH + (kb + tg) * BLD + tl]);
            uint32_t bh1 = __float_as_uint(sm[OFF_BH + (kb + tg + 4) * BLD + tl]);
            uint32_t bl0 = __float_as_uint(sm[OFF_BL + (kb + tg) * BLD + tl]);
            uint32_t bl1 = __float_as_uint(sm[OFF_BL + (kb + tg + 4) * BLD + tl]);
#pragma unroll
            for (int im = 0; im < 2; im++) {
                float* c = gc.acc[im][jf];
                mma_tf32(c[0], c[1], c[2], c[3],
                         al[im][0], al[im][1], al[im][2], al[im][3], bh0, bh1);
                mma_tf32(c[0], c[1], c[2], c[3],
                         ah[im][0], ah[im][1], ah[im][2], ah[im][3], bl0, bl1);
                mma_tf32(c[0], c[1], c[2], c[3],
                         ah[im][0], ah[im][1], ah[im][2], ah[im][3], bh0, bh1);
            }
        }
    }
}

// ---------------- GEMM with bias: Out[m,t] = sum_k W[m,k] X[k,t] + b[m] -------
__global__ __launch_bounds__(256) void gemm_tf32_bias(
    const float* __restrict__ Wm, const float* __restrict__ X,
    const float* __restrict__ bias, float* __restrict__ Out, int Kdim)
{
    extern __shared__ float sm[];
    const int tid = threadIdx.x;
    const int wid = tid >> 5, lane = tid & 31;
    const int g = lane >> 2, tg = lane & 3;
    const int bIdx = blockIdx.x >> 6;
    const int s0   = (blockIdx.x & 63) << 7;
    const int m0   = blockIdx.y << 7;
    const int wm = (wid & 3) << 5;
    const int wt = (wid >> 2) << 6;

    const float* Xb = X + (size_t)bIdx * Kdim * HWs + s0;
    float*       Ob = Out + (size_t)bIdx * Cdim * HWs + s0;

    GemmCore gc;
#pragma unroll
    for (int im = 0; im < 2; im++)
#pragma unroll
        for (int jf = 0; jf < 8; jf++)
#pragma unroll
            for (int e = 0; e < 4; e++) gc.acc[im][jf][e] = 0.f;

    const int bkr = tid >> 3;
    const int btc = (tid & 7) << 4;

    for (int k0 = 0; k0 < Kdim; k0 += 32) {
        load_a_tile(sm, Wm, m0, Kdim, k0, tid);
        load_b_row(sm, Xb + (size_t)(k0 + bkr) * HWs + btc, bkr, btc);
        __syncthreads();
        mma_chunk(sm, gc, wm, wt, g, tg);
        __syncthreads();
    }

#pragma unroll
    for (int im = 0; im < 2; im++) {
        const int m1 = m0 + wm + (im << 4) + g;
        const float bv1 = bias[m1], bv2 = bias[m1 + 8];
        float* o1 = Ob + (size_t)m1 * HWs;
        float* o2 = o1 + (size_t)8 * HWs;
#pragma unroll
        for (int jf = 0; jf < 8; jf++) {
            const int tl = wt + (jf << 3) + (tg << 1);
            const float* c = gc.acc[im][jf];
            *(float2*)(o1 + tl) = make_float2(c[0] + bv1, c[1] + bv1);
            *(float2*)(o2 + tl) = make_float2(c[2] + bv2, c[3] + bv2);
        }
    }
}

// ---------------- gate GEMM (K=768 concat) + fused sigmoid epilogue ----------
__global__ __launch_bounds__(256) void gemm_tf32_gate(
    const float* __restrict__ Wg, const float* __restrict__ FS,
    const float* __restrict__ OP, const float* __restrict__ bias,
    float* __restrict__ Fused)
{
    extern __shared__ float sm[];
    const int tid = threadIdx.x;
    const int wid = tid >> 5, lane = tid & 31;
    const int g = lane >> 2, tg = lane & 3;
    const int bIdx = blockIdx.x >> 6;
    const int s0   = (blockIdx.x & 63) << 7;
    const int m0   = blockIdx.y << 7;
    const int wm = (wid & 3) << 5;
    const int wt = (wid >> 2) << 6;

    const float* FSb = FS + (size_t)bIdx * Cdim * HWs + s0;
    const float* OPb = OP + (size_t)bIdx * Cdim * HWs + s0;
    float*       Fb  = Fused + (size_t)bIdx * Cdim * HWs + s0;

    GemmCore gc;
#pragma unroll
    for (int im = 0; im < 2; im++)
#pragma unroll
        for (int jf = 0; jf < 8; jf++)
#pragma unroll
            for (int e = 0; e < 4; e++) gc.acc[im][jf][e] = 0.f;

    const int bkr = tid >> 3;
    const int btc = (tid & 7) << 4;

    for (int k0 = 0; k0 < 768; k0 += 32) {
        load_a_tile(sm, Wg, m0, 768, k0, tid);
        const int kg = k0 + bkr;
        const float* xrow = (kg < Cdim) ? (FSb + (size_t)kg * HWs)
                                        : (OPb + (size_t)(kg - Cdim) * HWs);
        load_b_row(sm, xrow + btc, bkr, btc);
        __syncthreads();
        mma_chunk(sm, gc, wm, wt, g, tg);
        __syncthreads();
    }

#pragma unroll
    for (int im = 0; im < 2; im++) {
        const int m1 = m0 + wm + (im << 4) + g;
        const float bv1 = bias[m1], bv2 = bias[m1 + 8];
        const size_t r1 = (size_t)m1 * HWs, r2 = r1 + (size_t)8 * HWs;
#pragma unroll
        for (int jf = 0; jf < 8; jf++) {
            const int tl = wt + (jf << 3) + (tg << 1);
            const float* c = gc.acc[im][jf];
            float2 f1 = *(const float2*)(FSb + r1 + tl);
            float2 p1 = *(const float2*)(OPb + r1 + tl);
            float2 f2 = *(const float2*)(FSb + r2 + tl);
            float2 p2 = *(const float2*)(OPb + r2 + tl);
            float g0 = 1.f / (1.f + __expf(-(c[0] + bv1)));
            float g1 = 1.f / (1.f + __expf(-(c[1] + bv1)));
            float g2 = 1.f / (1.f + __expf(-(c[2] + bv2)));
            float g3 = 1.f / (1.f + __expf(-(c[3] + bv2)));
            *(float2*)(Fb + r1 + tl) = make_float2(f1.x + g0 * p1.x, f1.y + g1 * p1.y);
            *(float2*)(Fb + r2 + tl) = make_float2(f2.x + g2 * p2.x, f2.y + g3 * p2.y);
        }
    }
}

// ---------------- per-row epipolar attention (Round-1 proven, verbatim) ------
#define VPAD 100
#define SPAD 132
__global__ __launch_bounds__(256) void attn_kernel(
    const float* __restrict__ Q, const float* __restrict__ K,
    const float* __restrict__ V, float* __restrict__ O)
{
    extern __shared__ float smf[];
    float* Qs = smf;                         // [96][128]
    float* Ks = Qs + HDd * Ww;               // [96][128]
    float* Vt = Ks + HDd * Ww;               // [128][VPAD]
    float* Ss = Vt + Ww * VPAD;              // [128][SPAD]

    const int gblk = blockIdx.x;
    const int h = gblk & 63;
    const int n = (gblk >> 6) & 3;
    const int b = gblk >> 8;
    const size_t base = ((size_t)b * Cdim + (size_t)n * HDd) * HWs + (size_t)h * Ww;
    const int tid = threadIdx.x;

    for (int i = tid; i < HDd * Ww; i += 256) {
        int c = i >> 7, w = i & 127;
        size_t a = base + (size_t)c * HWs + w;
        Qs[i] = Q[a];
        Ks[i] = K[a];
        Vt[w * VPAD + c] = V[a];
    }
    __syncthreads();

    const int w  = tid >> 1;
    const int vb = (tid & 1) << 6;
    float acc[64];
#pragma unroll
    for (int i = 0; i < 64; i++) acc[i] = 0.f;
    for (int c = 0; c < HDd; c++) {
        float qv = Qs[c * Ww + w];
        const float4* kr = (const float4*)(Ks + c * Ww + vb);
#pragma unroll
        for (int j = 0; j < 16; j++) {
            float4 kv = kr[j];
            acc[4*j+0] += qv * kv.x; acc[4*j+1] += qv * kv.y;
            acc[4*j+2] += qv * kv.z; acc[4*j+3] += qv * kv.w;
        }
    }
    const float sc = 0.10206207261596575f;   // 1/sqrt(96)
    float4* srow = (float4*)(Ss + w * SPAD + vb);
#pragma unroll
    for (int j = 0; j < 16; j++)
        srow[j] = make_float4(acc[4*j+0]*sc, acc[4*j+1]*sc, acc[4*j+2]*sc, acc[4*j+3]*sc);
    __syncthreads();

    if (tid < Ww) {
        float* r = Ss + tid * SPAD;
        float m = r[0];
#pragma unroll 4
        for (int v = 1; v < Ww; v++) m = fmaxf(m, r[v]);
        float s = 0.f;
#pragma unroll 4
        for (int v = 0; v < Ww; v++) { float e = __expf(r[v] - m); r[v] = e; s += e; }
        float inv = 1.f / s;
#pragma unroll 4
        for (int v = 0; v < Ww; v++) r[v] *= inv;
    }
    __syncthreads();

    const int cb = (tid & 1) * 48;
    float oacc[48];
#pragma unroll
    for (int i = 0; i < 48; i++) oacc[i] = 0.f;
    const float* prow = Ss + w * SPAD;
    for (int v = 0; v < Ww; v++) {
        float p = prow[v];
        const float4* vr = (const float4*)(Vt + v * VPAD + cb);
#pragma unroll
        for (int j = 0; j < 12; j++) {
            float4 vv = vr[j];
            oacc[4*j+0] += p * vv.x; oacc[4*j+1] += p * vv.y;
            oacc[4*j+2] += p * vv.z; oacc[4*j+3] += p * vv.w;
        }
    }
#pragma unroll
    for (int j = 0; j < 48; j++)
        O[base + (size_t)(cb + j) * HWs + w] = oacc[j];
}

// ---------------- BatchNorm: stats then apply (Round-1 proven) ---------------
__global__ __launch_bounds__(256) void bn_stats_kernel(
    const float* __restrict__ F, const float* __restrict__ gamma,
    const float* __restrict__ beta, float* __restrict__ scale,
    float* __restrict__ shift)
{
    const int c = blockIdx.x;
    const int tid = threadIdx.x;
    float s = 0.f, s2 = 0.f;
    for (int i = tid; i < Bb * HWs; i += 256) {
        int b = i >> 13, sp = i & 8191;
        float v = F[(size_t)b * Cdim * HWs + (size_t)c * HWs + sp];
        s += v; s2 += v * v;
    }
    __shared__ float rs[256], rs2[256];
    rs[tid] = s; rs2[tid] = s2;
    __syncthreads();
    for (int o = 128; o > 0; o >>= 1) {
        if (tid < o) { rs[tid] += rs[tid + o]; rs2[tid] += rs2[tid + o]; }
        __syncthreads();
    }
    if (tid == 0) {
        float mean = rs[0] * (1.f / 65536.f);
        float var  = rs2[0] * (1.f / 65536.f) - mean * mean;
        float sv = gamma[c] * rsqrtf(var + EPSI);
        scale[c] = sv;
        shift[c] = beta[c] - mean * sv;
    }
}

__global__ __launch_bounds__(256) void bn_apply_kernel(
    const float* __restrict__ F, const float* __restrict__ scale,
    const float* __restrict__ shift, float* __restrict__ Out)
{
    int idx = blockIdx.x * blockDim.x + threadIdx.x;   // float4 index
    if (idx >= NELEM / 4) return;
    int c = (idx >> 11) % Cdim;
    float sv = scale[c], sh = shift[c];
    float4 v = ((const float4*)F)[idx];
    float4 o = make_float4(v.x * sv + sh, v.y * sv + sh, v.z * sv + sh, v.w * sv + sh);
    ((float4*)Out)[idx] = o;
}

// ---------------- launch ------------------------------------------------------
extern "C" void kernel_launch(void* const* d_in, const int* in_sizes, int n_in,
                              void* d_out, int out_size)
{
    const float* fs    = (const float*)d_in[0];
    const float* fo    = (const float*)d_in[1];
    const float* wq    = (const float*)d_in[2];
    const float* bq    = (const float*)d_in[3];
    const float* wk    = (const float*)d_in[4];
    const float* bk    = (const float*)d_in[5];
    const float* wv    = (const float*)d_in[6];
    const float* bv    = (const float*)d_in[7];
    const float* wo    = (const float*)d_in[8];
    const float* bo    = (const float*)d_in[9];
    const float* wg    = (const float*)d_in[10];
    const float* bg    = (const float*)d_in[11];
    const float* gamma = (const float*)d_in[12];
    const float* beta  = (const float*)d_in[13];
    float* out = (float*)d_out;

    float *pQ, *pK, *pV, *pA, *pO, *pF, *pScale, *pShift;
    cudaGetSymbolAddress((void**)&pQ, g_Q);
    cudaGetSymbolAddress((void**)&pK, g_K);
    cudaGetSymbolAddress((void**)&pV, g_V);
    cudaGetSymbolAddress((void**)&pA, g_A);
    cudaGetSymbolAddress((void**)&pO, g_O);
    cudaGetSymbolAddress((void**)&pF, g_F);
    cudaGetSymbolAddress((void**)&pScale, g_scale);
    cudaGetSymbolAddress((void**)&pShift, g_shift);

    const int smem_gemm = SMEM_FLOATS * sizeof(float);   // 71680
    cudaFuncSetAttribute(gemm_tf32_bias, cudaFuncAttributeMaxDynamicSharedMemorySize, smem_gemm);
    cudaFuncSetAttribute(gemm_tf32_gate, cudaFuncAttributeMaxDynamicSharedMemorySize, smem_gemm);
    const int smem_attn = (HDd * Ww * 2 + Ww * VPAD + Ww * SPAD) * sizeof(float); // 217088
    cudaFuncSetAttribute(attn_kernel, cudaFuncAttributeMaxDynamicSharedMemorySize, smem_attn);

    dim3 ggrid(512, 3);
    gemm_tf32_bias<<<ggrid, 256, smem_gemm>>>(wq, fs, bq, pQ, Cdim);
    gemm_tf32_bias<<<ggrid, 256, smem_gemm>>>(wk, fo, bk, pK, Cdim);
    gemm_tf32_bias<<<ggrid, 256, smem_gemm>>>(wv, fo, bv, pV, Cdim);

    attn_kernel<<<Bb * NHh * Hh, 256, smem_attn>>>(pQ, pK, pV, pA);

    gemm_tf32_bias<<<ggrid, 256, smem_gemm>>>(wo, pA, bo, pO, Cdim);
    gemm_tf32_gate<<<ggrid, 256, smem_gemm>>>(wg, fs, pO, bg, pF);

    bn_stats_kernel<<<Cdim, 256>>>(pF, gamma, beta, pScale, pShift);
    bn_apply_kernel<<<NELEM / 4 / 256, 256>>>(pF, pScale, pShift, out);
}

// round 14
// speedup vs baseline: 1.5324x; 1.4481x over previous
#include <cuda_runtime.h>
#include <cuda_bf16.h>
#include <math.h>
#include <cstdint>

// Problem constants
#define Cdim 384
#define NHh  4
#define HDd  96
#define Hh   64
#define Ww   128
#define Bb   8
#define HWs  8192                 // H*W
#define NELEM 25165824            // B*C*H*W
#define EPSI 1e-5f

// ---------------- scratch (device globals; allocation-free) ----------------
__device__ float g_Q[NELEM];
__device__ float g_K[NELEM];
__device__ float g_V[NELEM];
__device__ float g_A[NELEM];   // attention output (pre-wo)
__device__ float g_O[NELEM];   // after wo projection
__device__ float g_F[NELEM];   // fused (pre-BN)
__device__ float g_scale[Cdim];
__device__ float g_shift[Cdim];

// ---------------- bf16 helpers ----------------------------------------------
__device__ __forceinline__ unsigned short bfu(float x) {
    __nv_bfloat16 h = __float2bfloat16(x);
    return *reinterpret_cast<unsigned short*>(&h);
}
__device__ __forceinline__ float bff(unsigned short u) {
    __nv_bfloat16 h = *reinterpret_cast<__nv_bfloat16*>(&u);
    return __bfloat162float(h);
}

__device__ __forceinline__ void mma_bf16(
    float* c, uint32_t a0, uint32_t a1, uint32_t a2, uint32_t a3,
    uint32_t b0, uint32_t b1)
{
    asm volatile(
        "mma.sync.aligned.m16n8k16.row.col.f32.bf16.bf16.f32 "
        "{%0,%1,%2,%3}, {%4,%5,%6,%7}, {%8,%9}, {%0,%1,%2,%3};"
        : "+f"(c[0]), "+f"(c[1]), "+f"(c[2]), "+f"(c[3])
        : "r"(a0), "r"(a1), "r"(a2), "r"(a3), "r"(b0), "r"(b1));
}

#define LDMX4(r0, r1, r2, r3, addr) \
    asm volatile("ldmatrix.sync.aligned.m8n8.x4.shared.b16 {%0,%1,%2,%3}, [%4];" \
        : "=r"(r0), "=r"(r1), "=r"(r2), "=r"(r3) : "r"(addr))
#define LDMX4T(r0, r1, r2, r3, addr) \
    asm volatile("ldmatrix.sync.aligned.m8n8.x4.trans.shared.b16 {%0,%1,%2,%3}, [%4];" \
        : "=r"(r0), "=r"(r1), "=r"(r2), "=r"(r3) : "r"(addr))

__device__ __forceinline__ uint32_t smem_u32(const void* p) {
    uint32_t a;
    asm("{ .reg .u64 t; cvta.to.shared.u64 t, %1; cvt.u32.u64 %0, t; }" : "=r"(a) : "l"(p));
    return a;
}

// smem geometry (bytes): A tiles [128 rows][40 bf16] pitch 80B; B tiles [32][136] pitch 272B
#define OFF_AH 0
#define OFF_AL 10240
#define OFF_BH 20480
#define OFF_BL 29184
#define SMEM_BYTES 37888

// split one float into bf16 hi + bf16 lo(residual), packed pairs (low halfword = even k)
__device__ __forceinline__ void split_store4(
    char* smb, uint32_t off_hi, uint32_t off_lo, float4 v)
{
    unsigned short h0 = bfu(v.x), h1 = bfu(v.y), h2 = bfu(v.z), h3 = bfu(v.w);
    unsigned short l0 = bfu(v.x - bff(h0)), l1 = bfu(v.y - bff(h1));
    unsigned short l2 = bfu(v.z - bff(h2)), l3 = bfu(v.w - bff(h3));
    uint2 hp = make_uint2((uint32_t)h0 | ((uint32_t)h1 << 16),
                          (uint32_t)h2 | ((uint32_t)h3 << 16));
    uint2 lp = make_uint2((uint32_t)l0 | ((uint32_t)l1 << 16),
                          (uint32_t)l2 | ((uint32_t)l3 << 16));
    *(uint2*)(smb + off_hi) = hp;
    *(uint2*)(smb + off_lo) = lp;
}

// ---------------- GEMM mainloop body (macro'd inline via function) -----------
// acc[2][8][4] per warp; A = W[m,k] (row-major, stride Kdim); B = X[k,t].
struct Acc { float a[2][8][4]; };

__device__ __forceinline__ void gemm_chunk_mma(
    char* smb, Acc& gc, uint32_t a_lane, uint32_t b_lane)
{
#pragma unroll
    for (int ks = 0; ks < 2; ks++) {
        uint32_t ah[2][4], al[2][4];
#pragma unroll
        for (int im = 0; im < 2; im++) {
            const uint32_t aaddr = a_lane + im * 1280 + ks * 32;
            LDMX4(ah[im][0], ah[im][1], ah[im][2], ah[im][3], aaddr);
            LDMX4(al[im][0], al[im][1], al[im][2], al[im][3], aaddr + (OFF_AL - OFF_AH));
        }
#pragma unroll
        for (int jp = 0; jp < 4; jp++) {
            const uint32_t baddr = b_lane + jp * 32 + ks * 4352;
            uint32_t bh0, bh1, bh2, bh3, bl0, bl1, bl2, bl3;
            LDMX4T(bh0, bh1, bh2, bh3, baddr);
            LDMX4T(bl0, bl1, bl2, bl3, baddr + (OFF_BL - OFF_BH));
#pragma unroll
            for (int im = 0; im < 2; im++) {
                float* c0 = gc.a[im][2 * jp];
                float* c1 = gc.a[im][2 * jp + 1];
                mma_bf16(c0, ah[im][0], ah[im][1], ah[im][2], ah[im][3], bh0, bh1);
                mma_bf16(c0, ah[im][0], ah[im][1], ah[im][2], ah[im][3], bl0, bl1);
                mma_bf16(c0, al[im][0], al[im][1], al[im][2], al[im][3], bh0, bh1);
                mma_bf16(c1, ah[im][0], ah[im][1], ah[im][2], ah[im][3], bh2, bh3);
                mma_bf16(c1, ah[im][0], ah[im][1], ah[im][2], ah[im][3], bl2, bl3);
                mma_bf16(c1, al[im][0], al[im][1], al[im][2], al[im][3], bh2, bh3);
            }
        }
    }
}

// ---------------- GEMM with bias: Out[m,t] = sum_k W[m,k] X[k,t] + b[m] -------
__global__ __launch_bounds__(256, 2) void gemm_bf16_bias(
    const float* __restrict__ Wm, const float* __restrict__ X,
    const float* __restrict__ bias, float* __restrict__ Out, int Kdim)
{
    extern __shared__ char smb[];
    const int tid = threadIdx.x;
    const int wid = tid >> 5, lane = tid & 31;
    const int g = lane >> 2, tg = lane & 3;
    const int bIdx = blockIdx.x >> 6;
    const int s0   = (blockIdx.x & 63) << 7;
    const int m0   = blockIdx.y << 7;
    const int wm = (wid & 3) << 5;
    const int wt = (wid >> 2) << 6;

    const float* Xb = X + (size_t)bIdx * Kdim * HWs + s0;
    float*       Ob = Out + (size_t)bIdx * Cdim * HWs + s0;

    Acc gc;
#pragma unroll
    for (int im = 0; im < 2; im++)
#pragma unroll
        for (int jf = 0; jf < 8; jf++)
#pragma unroll
            for (int e = 0; e < 4; e++) gc.a[im][jf][e] = 0.f;

    const uint32_t smu = smem_u32(smb);
    const uint32_t a_lane = smu + OFF_AH + (wm + (lane & 15)) * 80 + (lane >> 4) * 16;
    const uint32_t b_lane = smu + OFF_BH + (lane & 15) * 272 + (lane >> 4) * 16 + wt * 2;

    const int arow = tid >> 1, akc = (tid & 1) << 4;
    const int bkr = tid >> 3, btc = (tid & 7) << 4;
    const uint32_t a_st = OFF_AH + arow * 80 + akc * 2;
    const uint32_t b_st = OFF_BH + bkr * 272 + btc * 2;

    for (int k0 = 0; k0 < Kdim; k0 += 32) {
        const float* wrow = Wm + (size_t)(m0 + arow) * Kdim + k0 + akc;
        const float* xrow = Xb + (size_t)(k0 + bkr) * HWs + btc;
#pragma unroll
        for (int u = 0; u < 4; u++) {
            split_store4(smb, a_st + u * 8, a_st + u * 8 + (OFF_AL - OFF_AH),
                         *(const float4*)(wrow + u * 4));
            split_store4(smb, b_st + u * 8, b_st + u * 8 + (OFF_BL - OFF_BH),
                         *(const float4*)(xrow + u * 4));
        }
        __syncthreads();
        gemm_chunk_mma(smb, gc, a_lane, b_lane);
        __syncthreads();
    }

#pragma unroll
    for (int im = 0; im < 2; im++) {
        const int m1 = m0 + wm + (im << 4) + g;
        const float bv1 = bias[m1], bv2 = bias[m1 + 8];
        float* o1 = Ob + (size_t)m1 * HWs;
        float* o2 = o1 + (size_t)8 * HWs;
#pragma unroll
        for (int jf = 0; jf < 8; jf++) {
            const int tl = wt + (jf << 3) + (tg << 1);
            const float* c = gc.a[im][jf];
            *(float2*)(o1 + tl) = make_float2(c[0] + bv1, c[1] + bv1);
            *(float2*)(o2 + tl) = make_float2(c[2] + bv2, c[3] + bv2);
        }
    }
}

// ---------------- gate GEMM (K=768 concat) + fused sigmoid epilogue ----------
__global__ __launch_bounds__(256, 2) void gemm_bf16_gate(
    const float* __restrict__ Wg, const float* __restrict__ FS,
    const float* __restrict__ OP, const float* __restrict__ bias,
    float* __restrict__ Fused)
{
    extern __shared__ char smb[];
    const int tid = threadIdx.x;
    const int wid = tid >> 5, lane = tid & 31;
    const int g = lane >> 2, tg = lane & 3;
    const int bIdx = blockIdx.x >> 6;
    const int s0   = (blockIdx.x & 63) << 7;
    const int m0   = blockIdx.y << 7;
    const int wm = (wid & 3) << 5;
    const int wt = (wid >> 2) << 6;

    const float* FSb = FS + (size_t)bIdx * Cdim * HWs + s0;
    const float* OPb = OP + (size_t)bIdx * Cdim * HWs + s0;
    float*       Fb  = Fused + (size_t)bIdx * Cdim * HWs + s0;

    Acc gc;
#pragma unroll
    for (int im = 0; im < 2; im++)
#pragma unroll
        for (int jf = 0; jf < 8; jf++)
#pragma unroll
            for (int e = 0; e < 4; e++) gc.a[im][jf][e] = 0.f;

    const uint32_t smu = smem_u32(smb);
    const uint32_t a_lane = smu + OFF_AH + (wm + (lane & 15)) * 80 + (lane >> 4) * 16;
    const uint32_t b_lane = smu + OFF_BH + (lane & 15) * 272 + (lane >> 4) * 16 + wt * 2;

    const int arow = tid >> 1, akc = (tid & 1) << 4;
    const int bkr = tid >> 3, btc = (tid & 7) << 4;
    const uint32_t a_st = OFF_AH + arow * 80 + akc * 2;
    const uint32_t b_st = OFF_BH + bkr * 272 + btc * 2;

    for (int k0 = 0; k0 < 768; k0 += 32) {
        const float* wrow = Wg + (size_t)(m0 + arow) * 768 + k0 + akc;
        const int kg = k0 + bkr;
        const float* xrow = (kg < Cdim) ? (FSb + (size_t)kg * HWs)
                                        : (OPb + (size_t)(kg - Cdim) * HWs);
        xrow += btc;
#pragma unroll
        for (int u = 0; u < 4; u++) {
            split_store4(smb, a_st + u * 8, a_st + u * 8 + (OFF_AL - OFF_AH),
                         *(const float4*)(wrow + u * 4));
            split_store4(smb, b_st + u * 8, b_st + u * 8 + (OFF_BL - OFF_BH),
                         *(const float4*)(xrow + u * 4));
        }
        __syncthreads();
        gemm_chunk_mma(smb, gc, a_lane, b_lane);
        __syncthreads();
    }

#pragma unroll
    for (int im = 0; im < 2; im++) {
        const int m1 = m0 + wm + (im << 4) + g;
        const float bv1 = bias[m1], bv2 = bias[m1 + 8];
        const size_t r1 = (size_t)m1 * HWs, r2 = r1 + (size_t)8 * HWs;
#pragma unroll
        for (int jf = 0; jf < 8; jf++) {
            const int tl = wt + (jf << 3) + (tg << 1);
            const float* c = gc.a[im][jf];
            float2 f1 = *(const float2*)(FSb + r1 + tl);
            float2 p1 = *(const float2*)(OPb + r1 + tl);
            float2 f2 = *(const float2*)(FSb + r2 + tl);
            float2 p2 = *(const float2*)(OPb + r2 + tl);
            float g0 = 1.f / (1.f + __expf(-(c[0] + bv1)));
            float g1 = 1.f / (1.f + __expf(-(c[1] + bv1)));
            float g2 = 1.f / (1.f + __expf(-(c[2] + bv2)));
            float g3 = 1.f / (1.f + __expf(-(c[3] + bv2)));
            *(float2*)(Fb + r1 + tl) = make_float2(f1.x + g0 * p1.x, f1.y + g1 * p1.y);
            *(float2*)(Fb + r2 + tl) = make_float2(f2.x + g2 * p2.x, f2.y + g3 * p2.y);
        }
    }
}

// ---------------- per-row epipolar attention (Round-1 proven, verbatim) ------
#define VPAD 100
#define SPAD 132
__global__ __launch_bounds__(256) void attn_kernel(
    const float* __restrict__ Q, const float* __restrict__ K,
    const float* __restrict__ V, float* __restrict__ O)
{
    extern __shared__ float smf[];
    float* Qs = smf;                         // [96][128]
    float* Ks = Qs + HDd * Ww;               // [96][128]
    float* Vt = Ks + HDd * Ww;               // [128][VPAD]
    float* Ss = Vt + Ww * VPAD;              // [128][SPAD]

    const int gblk = blockIdx.x;
    const int h = gblk & 63;
    const int n = (gblk >> 6) & 3;
    const int b = gblk >> 8;
    const size_t base = ((size_t)b * Cdim + (size_t)n * HDd) * HWs + (size_t)h * Ww;
    const int tid = threadIdx.x;

    for (int i = tid; i < HDd * Ww; i += 256) {
        int c = i >> 7, w = i & 127;
        size_t a = base + (size_t)c * HWs + w;
        Qs[i] = Q[a];
        Ks[i] = K[a];
        Vt[w * VPAD + c] = V[a];
    }
    __syncthreads();

    const int w  = tid >> 1;
    const int vb = (tid & 1) << 6;
    float acc[64];
#pragma unroll
    for (int i = 0; i < 64; i++) acc[i] = 0.f;
    for (int c = 0; c < HDd; c++) {
        float qv = Qs[c * Ww + w];
        const float4* kr = (const float4*)(Ks + c * Ww + vb);
#pragma unroll
        for (int j = 0; j < 16; j++) {
            float4 kv = kr[j];
            acc[4*j+0] += qv * kv.x; acc[4*j+1] += qv * kv.y;
            acc[4*j+2] += qv * kv.z; acc[4*j+3] += qv * kv.w;
        }
    }
    const float sc = 0.10206207261596575f;   // 1/sqrt(96)
    float4* srow = (float4*)(Ss + w * SPAD + vb);
#pragma unroll
    for (int j = 0; j < 16; j++)
        srow[j] = make_float4(acc[4*j+0]*sc, acc[4*j+1]*sc, acc[4*j+2]*sc, acc[4*j+3]*sc);
    __syncthreads();

    if (tid < Ww) {
        float* r = Ss + tid * SPAD;
        float m = r[0];
#pragma unroll 4
        for (int v = 1; v < Ww; v++) m = fmaxf(m, r[v]);
        float s = 0.f;
#pragma unroll 4
        for (int v = 0; v < Ww; v++) { float e = __expf(r[v] - m); r[v] = e; s += e; }
        float inv = 1.f / s;
#pragma unroll 4
        for (int v = 0; v < Ww; v++) r[v] *= inv;
    }
    __syncthreads();

    const int cb = (tid & 1) * 48;
    float oacc[48];
#pragma unroll
    for (int i = 0; i < 48; i++) oacc[i] = 0.f;
    const float* prow = Ss + w * SPAD;
    for (int v = 0; v < Ww; v++) {
        float p = prow[v];
        const float4* vr = (const float4*)(Vt + v * VPAD + cb);
#pragma unroll
        for (int j = 0; j < 12; j++) {
            float4 vv = vr[j];
            oacc[4*j+0] += p * vv.x; oacc[4*j+1] += p * vv.y;
            oacc[4*j+2] += p * vv.z; oacc[4*j+3] += p * vv.w;
        }
    }
#pragma unroll
    for (int j = 0; j < 48; j++)
        O[base + (size_t)(cb + j) * HWs + w] = oacc[j];
}

// ---------------- BatchNorm: stats then apply (Round-1 proven) ---------------
__global__ __launch_bounds__(256) void bn_stats_kernel(
    const float* __restrict__ F, const float* __restrict__ gamma,
    const float* __restrict__ beta, float* __restrict__ scale,
    float* __restrict__ shift)
{
    const int c = blockIdx.x;
    const int tid = threadIdx.x;
    float s = 0.f, s2 = 0.f;
    for (int i = tid; i < Bb * HWs; i += 256) {
        int b = i >> 13, sp = i & 8191;
        float v = F[(size_t)b * Cdim * HWs + (size_t)c * HWs + sp];
        s += v; s2 += v * v;
    }
    __shared__ float rs[256], rs2[256];
    rs[tid] = s; rs2[tid] = s2;
    __syncthreads();
    for (int o = 128; o > 0; o >>= 1) {
        if (tid < o) { rs[tid] += rs[tid + o]; rs2[tid] += rs2[tid + o]; }
        __syncthreads();
    }
    if (tid == 0) {
        float mean = rs[0] * (1.f / 65536.f);
        float var  = rs2[0] * (1.f / 65536.f) - mean * mean;
        float sv = gamma[c] * rsqrtf(var + EPSI);
        scale[c] = sv;
        shift[c] = beta[c] - mean * sv;
    }
}

__global__ __launch_bounds__(256) void bn_apply_kernel(
    const float* __restrict__ F, const float* __restrict__ scale,
    const float* __restrict__ shift, float* __restrict__ Out)
{
    int idx = blockIdx.x * blockDim.x + threadIdx.x;   // float4 index
    if (idx >= NELEM / 4) return;
    int c = (idx >> 11) % Cdim;
    float sv = scale[c], sh = shift[c];
    float4 v = ((const float4*)F)[idx];
    float4 o = make_float4(v.x * sv + sh, v.y * sv + sh, v.z * sv + sh, v.w * sv + sh);
    ((float4*)Out)[idx] = o;
}

// ---------------- launch ------------------------------------------------------
extern "C" void kernel_launch(void* const* d_in, const int* in_sizes, int n_in,
                              void* d_out, int out_size)
{
    const float* fs    = (const float*)d_in[0];
    const float* fo    = (const float*)d_in[1];
    const float* wq    = (const float*)d_in[2];
    const float* bq    = (const float*)d_in[3];
    const float* wk    = (const float*)d_in[4];
    const float* bk    = (const float*)d_in[5];
    const float* wv    = (const float*)d_in[6];
    const float* bv    = (const float*)d_in[7];
    const float* wo    = (const float*)d_in[8];
    const float* bo    = (const float*)d_in[9];
    const float* wg    = (const float*)d_in[10];
    const float* bg    = (const float*)d_in[11];
    const float* gamma = (const float*)d_in[12];
    const float* beta  = (const float*)d_in[13];
    float* out = (float*)d_out;

    float *pQ, *pK, *pV, *pA, *pO, *pF, *pScale, *pShift;
    cudaGetSymbolAddress((void**)&pQ, g_Q);
    cudaGetSymbolAddress((void**)&pK, g_K);
    cudaGetSymbolAddress((void**)&pV, g_V);
    cudaGetSymbolAddress((void**)&pA, g_A);
    cudaGetSymbolAddress((void**)&pO, g_O);
    cudaGetSymbolAddress((void**)&pF, g_F);
    cudaGetSymbolAddress((void**)&pScale, g_scale);
    cudaGetSymbolAddress((void**)&pShift, g_shift);

    const int smem_attn = (HDd * Ww * 2 + Ww * VPAD + Ww * SPAD) * sizeof(float); // 217088
    cudaFuncSetAttribute(attn_kernel, cudaFuncAttributeMaxDynamicSharedMemorySize, smem_attn);

    dim3 ggrid(512, 3);
    gemm_bf16_bias<<<ggrid, 256, SMEM_BYTES>>>(wq, fs, bq, pQ, Cdim);
    gemm_bf16_bias<<<ggrid, 256, SMEM_BYTES>>>(wk, fo, bk, pK, Cdim);
    gemm_bf16_bias<<<ggrid, 256, SMEM_BYTES>>>(wv, fo, bv, pV, Cdim);

    attn_kernel<<<Bb * NHh * Hh, 256, smem_attn>>>(pQ, pK, pV, pA);

    gemm_bf16_bias<<<ggrid, 256, SMEM_BYTES>>>(wo, pA, bo, pO, Cdim);
    gemm_bf16_gate<<<ggrid, 256, SMEM_BYTES>>>(wg, fs, pO, bg, pF);

    bn_stats_kernel<<<Cdim, 256>>>(pF, gamma, beta, pScale, pShift);
    bn_apply_kernel<<<NELEM / 4 / 256, 256>>>(pF, pScale, pShift, out);
}

// round 15
// speedup vs baseline: 1.9739x; 1.2881x over previous
#include <cuda_runtime.h>
#include <cuda_bf16.h>
#include <math.h>
#include <cstdint>

// Problem constants
#define Cdim 384
#define NHh  4
#define HDd  96
#define Hh   64
#define Ww   128
#define Bb   8
#define HWs  8192                 // H*W
#define NELEM 25165824            // B*C*H*W
#define EPSI 1e-5f

// ---------------- scratch (device globals; allocation-free) ----------------
__device__ float g_Q[NELEM];
__device__ float g_K[NELEM];
__device__ float g_V[NELEM];
__device__ float g_A[NELEM];   // attention output (pre-wo)
__device__ float g_O[NELEM];   // after wo projection
__device__ float g_F[NELEM];   // fused (pre-BN)
__device__ float g_scale[Cdim];
__device__ float g_shift[Cdim];

// ---------------- bf16 helpers ----------------------------------------------
__device__ __forceinline__ unsigned short bfu(float x) {
    __nv_bfloat16 h = __float2bfloat16(x);
    return *reinterpret_cast<unsigned short*>(&h);
}
__device__ __forceinline__ float bff(unsigned short u) {
    __nv_bfloat16 h = *reinterpret_cast<__nv_bfloat16*>(&u);
    return __bfloat162float(h);
}

__device__ __forceinline__ void mma_bf16(
    float* c, uint32_t a0, uint32_t a1, uint32_t a2, uint32_t a3,
    uint32_t b0, uint32_t b1)
{
    asm volatile(
        "mma.sync.aligned.m16n8k16.row.col.f32.bf16.bf16.f32 "
        "{%0,%1,%2,%3}, {%4,%5,%6,%7}, {%8,%9}, {%0,%1,%2,%3};"
        : "+f"(c[0]), "+f"(c[1]), "+f"(c[2]), "+f"(c[3])
        : "r"(a0), "r"(a1), "r"(a2), "r"(a3), "r"(b0), "r"(b1));
}

#define LDMX4(r0, r1, r2, r3, addr) \
    asm volatile("ldmatrix.sync.aligned.m8n8.x4.shared.b16 {%0,%1,%2,%3}, [%4];" \
        : "=r"(r0), "=r"(r1), "=r"(r2), "=r"(r3) : "r"(addr))
#define LDMX4T(r0, r1, r2, r3, addr) \
    asm volatile("ldmatrix.sync.aligned.m8n8.x4.trans.shared.b16 {%0,%1,%2,%3}, [%4];" \
        : "=r"(r0), "=r"(r1), "=r"(r2), "=r"(r3) : "r"(addr))

__device__ __forceinline__ uint32_t smem_u32(const void* p) {
    uint32_t a;
    asm("{ .reg .u64 t; cvta.to.shared.u64 t, %1; cvt.u32.u64 %0, t; }" : "=r"(a) : "l"(p));
    return a;
}

// smem geometry (bytes): A tiles [128 rows][40 bf16] pitch 80B; B tiles [32][136] pitch 272B
#define OFF_AH 0
#define OFF_AL 10240
#define OFF_BH 20480
#define OFF_BL 29184
#define SMEM_BYTES 37888

// split one float into bf16 hi + bf16 lo(residual), packed pairs (low halfword = even k)
__device__ __forceinline__ void split_store4(
    char* smb, uint32_t off_hi, uint32_t off_lo, float4 v)
{
    unsigned short h0 = bfu(v.x), h1 = bfu(v.y), h2 = bfu(v.z), h3 = bfu(v.w);
    unsigned short l0 = bfu(v.x - bff(h0)), l1 = bfu(v.y - bff(h1));
    unsigned short l2 = bfu(v.z - bff(h2)), l3 = bfu(v.w - bff(h3));
    uint2 hp = make_uint2((uint32_t)h0 | ((uint32_t)h1 << 16),
                          (uint32_t)h2 | ((uint32_t)h3 << 16));
    uint2 lp = make_uint2((uint32_t)l0 | ((uint32_t)l1 << 16),
                          (uint32_t)l2 | ((uint32_t)l3 << 16));
    *(uint2*)(smb + off_hi) = hp;
    *(uint2*)(smb + off_lo) = lp;
}

#define SPLITPACK(ph, pl, x, y) do { \
    unsigned short _hx = bfu(x), _hy = bfu(y); \
    ph = (uint32_t)_hx | ((uint32_t)_hy << 16); \
    pl = (uint32_t)bfu((x) - bff(_hx)) | ((uint32_t)bfu((y) - bff(_hy)) << 16); \
} while (0)

// ---------------- GEMM mainloop body ----------------------------------------
struct Acc { float a[2][8][4]; };

__device__ __forceinline__ void gemm_chunk_mma(
    char* smb, Acc& gc, uint32_t a_lane, uint32_t b_lane)
{
#pragma unroll
    for (int ks = 0; ks < 2; ks++) {
        uint32_t ah[2][4], al[2][4];
#pragma unroll
        for (int im = 0; im < 2; im++) {
            const uint32_t aaddr = a_lane + im * 1280 + ks * 32;
            LDMX4(ah[im][0], ah[im][1], ah[im][2], ah[im][3], aaddr);
            LDMX4(al[im][0], al[im][1], al[im][2], al[im][3], aaddr + (OFF_AL - OFF_AH));
        }
#pragma unroll
        for (int jp = 0; jp < 4; jp++) {
            const uint32_t baddr = b_lane + jp * 32 + ks * 4352;
            uint32_t bh0, bh1, bh2, bh3, bl0, bl1, bl2, bl3;
            LDMX4T(bh0, bh1, bh2, bh3, baddr);
            LDMX4T(bl0, bl1, bl2, bl3, baddr + (OFF_BL - OFF_BH));
#pragma unroll
            for (int im = 0; im < 2; im++) {
                float* c0 = gc.a[im][2 * jp];
                float* c1 = gc.a[im][2 * jp + 1];
                mma_bf16(c0, ah[im][0], ah[im][1], ah[im][2], ah[im][3], bh0, bh1);
                mma_bf16(c0, ah[im][0], ah[im][1], ah[im][2], ah[im][3], bl0, bl1);
                mma_bf16(c0, al[im][0], al[im][1], al[im][2], al[im][3], bh0, bh1);
                mma_bf16(c1, ah[im][0], ah[im][1], ah[im][2], ah[im][3], bh2, bh3);
                mma_bf16(c1, ah[im][0], ah[im][1], ah[im][2], ah[im][3], bl2, bl3);
                mma_bf16(c1, al[im][0], al[im][1], al[im][2], al[im][3], bh2, bh3);
            }
        }
    }
}

// ---------------- GEMM with bias: Out[m,t] = sum_k W[m,k] X[k,t] + b[m] -------
__global__ __launch_bounds__(256, 2) void gemm_bf16_bias(
    const float* __restrict__ Wm, const float* __restrict__ X,
    const float* __restrict__ bias, float* __restrict__ Out, int Kdim)
{
    extern __shared__ char smb[];
    const int tid = threadIdx.x;
    const int wid = tid >> 5, lane = tid & 31;
    const int g = lane >> 2, tg = lane & 3;
    const int bIdx = blockIdx.x >> 6;
    const int s0   = (blockIdx.x & 63) << 7;
    const int m0   = blockIdx.y << 7;
    const int wm = (wid & 3) << 5;
    const int wt = (wid >> 2) << 6;

    const float* Xb = X + (size_t)bIdx * Kdim * HWs + s0;
    float*       Ob = Out + (size_t)bIdx * Cdim * HWs + s0;

    Acc gc;
#pragma unroll
    for (int im = 0; im < 2; im++)
#pragma unroll
        for (int jf = 0; jf < 8; jf++)
#pragma unroll
            for (int e = 0; e < 4; e++) gc.a[im][jf][e] = 0.f;

    const uint32_t smu = smem_u32(smb);
    const uint32_t a_lane = smu + OFF_AH + (wm + (lane & 15)) * 80 + (lane >> 4) * 16;
    const uint32_t b_lane = smu + OFF_BH + (lane & 15) * 272 + (lane >> 4) * 16 + wt * 2;

    const int arow = tid >> 1, akc = (tid & 1) << 4;
    const int bkr = tid >> 3, btc = (tid & 7) << 4;
    const uint32_t a_st = OFF_AH + arow * 80 + akc * 2;
    const uint32_t b_st = OFF_BH + bkr * 272 + btc * 2;

    for (int k0 = 0; k0 < Kdim; k0 += 32) {
        const float* wrow = Wm + (size_t)(m0 + arow) * Kdim + k0 + akc;
        const float* xrow = Xb + (size_t)(k0 + bkr) * HWs + btc;
#pragma unroll
        for (int u = 0; u < 4; u++) {
            split_store4(smb, a_st + u * 8, a_st + u * 8 + (OFF_AL - OFF_AH),
                         *(const float4*)(wrow + u * 4));
            split_store4(smb, b_st + u * 8, b_st + u * 8 + (OFF_BL - OFF_BH),
                         *(const float4*)(xrow + u * 4));
        }
        __syncthreads();
        gemm_chunk_mma(smb, gc, a_lane, b_lane);
        __syncthreads();
    }

#pragma unroll
    for (int im = 0; im < 2; im++) {
        const int m1 = m0 + wm + (im << 4) + g;
        const float bv1 = bias[m1], bv2 = bias[m1 + 8];
        float* o1 = Ob + (size_t)m1 * HWs;
        float* o2 = o1 + (size_t)8 * HWs;
#pragma unroll
        for (int jf = 0; jf < 8; jf++) {
            const int tl = wt + (jf << 3) + (tg << 1);
            const float* c = gc.a[im][jf];
            *(float2*)(o1 + tl) = make_float2(c[0] + bv1, c[1] + bv1);
            *(float2*)(o2 + tl) = make_float2(c[2] + bv2, c[3] + bv2);
        }
    }
}

// ---------------- gate GEMM (K=768 concat) + fused sigmoid epilogue ----------
__global__ __launch_bounds__(256, 2) void gemm_bf16_gate(
    const float* __restrict__ Wg, const float* __restrict__ FS,
    const float* __restrict__ OP, const float* __restrict__ bias,
    float* __restrict__ Fused)
{
    extern __shared__ char smb[];
    const int tid = threadIdx.x;
    const int wid = tid >> 5, lane = tid & 31;
    const int g = lane >> 2, tg = lane & 3;
    const int bIdx = blockIdx.x >> 6;
    const int s0   = (blockIdx.x & 63) << 7;
    const int m0   = blockIdx.y << 7;
    const int wm = (wid & 3) << 5;
    const int wt = (wid >> 2) << 6;

    const float* FSb = FS + (size_t)bIdx * Cdim * HWs + s0;
    const float* OPb = OP + (size_t)bIdx * Cdim * HWs + s0;
    float*       Fb  = Fused + (size_t)bIdx * Cdim * HWs + s0;

    Acc gc;
#pragma unroll
    for (int im = 0; im < 2; im++)
#pragma unroll
        for (int jf = 0; jf < 8; jf++)
#pragma unroll
            for (int e = 0; e < 4; e++) gc.a[im][jf][e] = 0.f;

    const uint32_t smu = smem_u32(smb);
    const uint32_t a_lane = smu + OFF_AH + (wm + (lane & 15)) * 80 + (lane >> 4) * 16;
    const uint32_t b_lane = smu + OFF_BH + (lane & 15) * 272 + (lane >> 4) * 16 + wt * 2;

    const int arow = tid >> 1, akc = (tid & 1) << 4;
    const int bkr = tid >> 3, btc = (tid & 7) << 4;
    const uint32_t a_st = OFF_AH + arow * 80 + akc * 2;
    const uint32_t b_st = OFF_BH + bkr * 272 + btc * 2;

    for (int k0 = 0; k0 < 768; k0 += 32) {
        const float* wrow = Wg + (size_t)(m0 + arow) * 768 + k0 + akc;
        const int kg = k0 + bkr;
        const float* xrow = (kg < Cdim) ? (FSb + (size_t)kg * HWs)
                                        : (OPb + (size_t)(kg - Cdim) * HWs);
        xrow += btc;
#pragma unroll
        for (int u = 0; u < 4; u++) {
            split_store4(smb, a_st + u * 8, a_st + u * 8 + (OFF_AL - OFF_AH),
                         *(const float4*)(wrow + u * 4));
            split_store4(smb, b_st + u * 8, b_st + u * 8 + (OFF_BL - OFF_BH),
                         *(const float4*)(xrow + u * 4));
        }
        __syncthreads();
        gemm_chunk_mma(smb, gc, a_lane, b_lane);
        __syncthreads();
    }

#pragma unroll
    for (int im = 0; im < 2; im++) {
        const int m1 = m0 + wm + (im << 4) + g;
        const float bv1 = bias[m1], bv2 = bias[m1 + 8];
        const size_t r1 = (size_t)m1 * HWs, r2 = r1 + (size_t)8 * HWs;
#pragma unroll
        for (int jf = 0; jf < 8; jf++) {
            const int tl = wt + (jf << 3) + (tg << 1);
            const float* c = gc.a[im][jf];
            float2 f1 = *(const float2*)(FSb + r1 + tl);
            float2 p1 = *(const float2*)(OPb + r1 + tl);
            float2 f2 = *(const float2*)(FSb + r2 + tl);
            float2 p2 = *(const float2*)(OPb + r2 + tl);
            float g0 = 1.f / (1.f + __expf(-(c[0] + bv1)));
            float g1 = 1.f / (1.f + __expf(-(c[1] + bv1)));
            float g2 = 1.f / (1.f + __expf(-(c[2] + bv2)));
            float g3 = 1.f / (1.f + __expf(-(c[3] + bv2)));
            *(float2*)(Fb + r1 + tl) = make_float2(f1.x + g0 * p1.x, f1.y + g1 * p1.y);
            *(float2*)(Fb + r2 + tl) = make_float2(f2.x + g2 * p2.x, f2.y + g3 * p2.y);
        }
    }
}

// ---------------- tensor-core epipolar attention ------------------------------
// One CTA per (b,n,h). S = Q K^T (k=c), softmax in registers, O = P V (k=v).
// smem: Q/K/V hi+lo, natural [c][*] layout, pitch 136 halves (272B, ldmatrix
// conflict-free). O staged via reused Q region, pitch 132 floats.
#define AQH 0
#define AQL 26112
#define AKH 52224
#define AKL 78336
#define AVH 104448
#define AVL 130560
#define ATT_SMEM 156672

__global__ __launch_bounds__(256, 1) void attn_mma(
    const float* __restrict__ Q, const float* __restrict__ K,
    const float* __restrict__ V, float* __restrict__ O)
{
    extern __shared__ char smb[];
    const uint32_t smu = smem_u32(smb);

    const int gblk = blockIdx.x;
    const int h = gblk & 63;
    const int n = (gblk >> 6) & 3;
    const int b = gblk >> 8;
    const size_t base = ((size_t)b * Cdim + (size_t)n * HDd) * HWs + (size_t)h * Ww;

    const int tid = threadIdx.x;
    const int wid = tid >> 5, lane = tid & 31;
    const int g = lane >> 2, tg = lane & 3;
    const int wm = wid << 4;                 // 16 w-rows per warp

    const float sc = 0.10206207261596575f;   // 1/sqrt(96)

    // ---- load Q,K,V into split smem (coalesced, natural layout) ----
    for (int i = tid; i < 96 * 32; i += 256) {
        const int c = i >> 5, w4 = (i & 31) << 2;
        const size_t a = base + (size_t)c * HWs + w4;
        const uint32_t ro = (uint32_t)c * 272 + (uint32_t)w4 * 2;
        float4 q = *(const float4*)(Q + a);
        q.x *= sc; q.y *= sc; q.z *= sc; q.w *= sc;
        split_store4(smb, AQH + ro, AQL + ro, q);
        split_store4(smb, AKH + ro, AKL + ro, *(const float4*)(K + a));
        split_store4(smb, AVH + ro, AVL + ro, *(const float4*)(V + a));
    }
    __syncthreads();

    // ---- S = Q K^T : warp computes rows [wm, wm+16) x all 128 v ----
    const uint32_t qaddr = smu + AQH
        + (uint32_t)((lane & 7) + ((lane >> 4) << 3)) * 272
        + (uint32_t)(wm + (((lane >> 3) & 1) << 3)) * 2;
    const uint32_t kaddr = smu + AKH
        + (uint32_t)(lane & 15) * 272 + (uint32_t)((lane >> 4) << 4);

    float sacc[16][4];
#pragma unroll
    for (int jf = 0; jf < 16; jf++)
#pragma unroll
        for (int e = 0; e < 4; e++) sacc[jf][e] = 0.f;

#pragma unroll
    for (int kc = 0; kc < 6; kc++) {
        uint32_t qh[4], ql[4];
        LDMX4T(qh[0], qh[1], qh[2], qh[3], qaddr + kc * 4352);
        LDMX4T(ql[0], ql[1], ql[2], ql[3], qaddr + kc * 4352 + (AQL - AQH));
#pragma unroll
        for (int jp = 0; jp < 8; jp++) {
            uint32_t kh0, kh1, kh2, kh3, kl0, kl1, kl2, kl3;
            const uint32_t ka = kaddr + kc * 4352 + jp * 32;
            LDMX4T(kh0, kh1, kh2, kh3, ka);
            LDMX4T(kl0, kl1, kl2, kl3, ka + (AKL - AKH));
            float* c0 = sacc[2 * jp];
            float* c1 = sacc[2 * jp + 1];
            mma_bf16(c0, qh[0], qh[1], qh[2], qh[3], kh0, kh1);
            mma_bf16(c0, qh[0], qh[1], qh[2], qh[3], kl0, kl1);
            mma_bf16(c0, ql[0], ql[1], ql[2], ql[3], kh0, kh1);
            mma_bf16(c1, qh[0], qh[1], qh[2], qh[3], kh2, kh3);
            mma_bf16(c1, qh[0], qh[1], qh[2], qh[3], kl2, kl3);
            mma_bf16(c1, ql[0], ql[1], ql[2], ql[3], kh2, kh3);
        }
    }
    __syncthreads();   // Q/K reads done; Q region may be reused for O staging

    // ---- softmax in registers (rows g and g+8, quad shfl reduction) ----
    float m0 = -1e30f, m1 = -1e30f;
#pragma unroll
    for (int jf = 0; jf < 16; jf++) {
        m0 = fmaxf(m0, fmaxf(sacc[jf][0], sacc[jf][1]));
        m1 = fmaxf(m1, fmaxf(sacc[jf][2], sacc[jf][3]));
    }
    m0 = fmaxf(m0, __shfl_xor_sync(0xffffffffu, m0, 1));
    m0 = fmaxf(m0, __shfl_xor_sync(0xffffffffu, m0, 2));
    m1 = fmaxf(m1, __shfl_xor_sync(0xffffffffu, m1, 1));
    m1 = fmaxf(m1, __shfl_xor_sync(0xffffffffu, m1, 2));
    float s0 = 0.f, s1 = 0.f;
#pragma unroll
    for (int jf = 0; jf < 16; jf++) {
        float e0 = __expf(sacc[jf][0] - m0);
        float e1 = __expf(sacc[jf][1] - m0);
        float e2 = __expf(sacc[jf][2] - m1);
        float e3 = __expf(sacc[jf][3] - m1);
        sacc[jf][0] = e0; sacc[jf][1] = e1; sacc[jf][2] = e2; sacc[jf][3] = e3;
        s0 += e0 + e1; s1 += e2 + e3;
    }
    s0 += __shfl_xor_sync(0xffffffffu, s0, 1);
    s0 += __shfl_xor_sync(0xffffffffu, s0, 2);
    s1 += __shfl_xor_sync(0xffffffffu, s1, 1);
    s1 += __shfl_xor_sync(0xffffffffu, s1, 2);
    const float i0 = 1.f / s0, i1 = 1.f / s1;
#pragma unroll
    for (int jf = 0; jf < 16; jf++) {
        sacc[jf][0] *= i0; sacc[jf][1] *= i0;
        sacc[jf][2] *= i1; sacc[jf][3] *= i1;
    }

    // ---- O = P V : P fragments repacked from registers, V via ldmatrix ----
    const uint32_t vaddr = smu + AVH
        + (uint32_t)((lane & 7) + ((lane >> 4) << 3)) * 272
        + (uint32_t)(((lane >> 3) & 1) << 4);

    float oacc[12][4];
#pragma unroll
    for (int jt = 0; jt < 12; jt++)
#pragma unroll
        for (int e = 0; e < 4; e++) oacc[jt][e] = 0.f;

#pragma unroll
    for (int kc = 0; kc < 8; kc++) {
        uint32_t ph[4], pl[4];
        SPLITPACK(ph[0], pl[0], sacc[2 * kc][0], sacc[2 * kc][1]);
        SPLITPACK(ph[1], pl[1], sacc[2 * kc][2], sacc[2 * kc][3]);
        SPLITPACK(ph[2], pl[2], sacc[2 * kc + 1][0], sacc[2 * kc + 1][1]);
        SPLITPACK(ph[3], pl[3], sacc[2 * kc + 1][2], sacc[2 * kc + 1][3]);
#pragma unroll
        for (int jc = 0; jc < 6; jc++) {
            uint32_t vh0, vh1, vh2, vh3, vl0, vl1, vl2, vl3;
            const uint32_t va = vaddr + jc * 4352 + kc * 32;
            LDMX4(vh0, vh1, vh2, vh3, va);
            LDMX4(vl0, vl1, vl2, vl3, va + (AVL - AVH));
            float* d0 = oacc[2 * jc];
            float* d1 = oacc[2 * jc + 1];
            mma_bf16(d0, ph[0], ph[1], ph[2], ph[3], vh0, vh1);
            mma_bf16(d0, ph[0], ph[1], ph[2], ph[3], vl0, vl1);
            mma_bf16(d0, pl[0], pl[1], pl[2], pl[3], vh0, vh1);
            mma_bf16(d1, ph[0], ph[1], ph[2], ph[3], vh2, vh3);
            mma_bf16(d1, ph[0], ph[1], ph[2], ph[3], vl2, vl3);
            mma_bf16(d1, pl[0], pl[1], pl[2], pl[3], vh2, vh3);
        }
    }

    // ---- stage O[c][w] through smem (pitch 132, conflict-free), then store ----
    float* Osm = (float*)smb;   // reuses Q region (96*132*4 = 50688 <= 52224)
#pragma unroll
    for (int jt = 0; jt < 12; jt++) {
        const int c = (jt << 3) + (tg << 1);
        const int w = wm + g;
        Osm[c * 132 + w]            = oacc[jt][0];
        Osm[(c + 1) * 132 + w]      = oacc[jt][1];
        Osm[c * 132 + w + 8]        = oacc[jt][2];
        Osm[(c + 1) * 132 + w + 8]  = oacc[jt][3];
    }
    __syncthreads();

    for (int i = tid; i < 96 * 32; i += 256) {
        const int c = i >> 5, w4 = (i & 31) << 2;
        *(float4*)(O + base + (size_t)c * HWs + w4) = *(const float4*)(Osm + c * 132 + w4);
    }
}

// ---------------- BatchNorm: stats then apply (Round-1 proven) ---------------
__global__ __launch_bounds__(256) void bn_stats_kernel(
    const float* __restrict__ F, const float* __restrict__ gamma,
    const float* __restrict__ beta, float* __restrict__ scale,
    float* __restrict__ shift)
{
    const int c = blockIdx.x;
    const int tid = threadIdx.x;
    float s = 0.f, s2 = 0.f;
    for (int i = tid; i < Bb * HWs; i += 256) {
        int b = i >> 13, sp = i & 8191;
        float v = F[(size_t)b * Cdim * HWs + (size_t)c * HWs + sp];
        s += v; s2 += v * v;
    }
    __shared__ float rs[256], rs2[256];
    rs[tid] = s; rs2[tid] = s2;
    __syncthreads();
    for (int o = 128; o > 0; o >>= 1) {
        if (tid < o) { rs[tid] += rs[tid + o]; rs2[tid] += rs2[tid + o]; }
        __syncthreads();
    }
    if (tid == 0) {
        float mean = rs[0] * (1.f / 65536.f);
        float var  = rs2[0] * (1.f / 65536.f) - mean * mean;
        float sv = gamma[c] * rsqrtf(var + EPSI);
        scale[c] = sv;
        shift[c] = beta[c] - mean * sv;
    }
}

__global__ __launch_bounds__(256) void bn_apply_kernel(
    const float* __restrict__ F, const float* __restrict__ scale,
    const float* __restrict__ shift, float* __restrict__ Out)
{
    int idx = blockIdx.x * blockDim.x + threadIdx.x;   // float4 index
    if (idx >= NELEM / 4) return;
    int c = (idx >> 11) % Cdim;
    float sv = scale[c], sh = shift[c];
    float4 v = ((const float4*)F)[idx];
    float4 o = make_float4(v.x * sv + sh, v.y * sv + sh, v.z * sv + sh, v.w * sv + sh);
    ((float4*)Out)[idx] = o;
}

// ---------------- launch ------------------------------------------------------
extern "C" void kernel_launch(void* const* d_in, const int* in_sizes, int n_in,
                              void* d_out, int out_size)
{
    const float* fs    = (const float*)d_in[0];
    const float* fo    = (const float*)d_in[1];
    const float* wq    = (const float*)d_in[2];
    const float* bq    = (const float*)d_in[3];
    const float* wk    = (const float*)d_in[4];
    const float* bk    = (const float*)d_in[5];
    const float* wv    = (const float*)d_in[6];
    const float* bv    = (const float*)d_in[7];
    const float* wo    = (const float*)d_in[8];
    const float* bo    = (const float*)d_in[9];
    const float* wg    = (const float*)d_in[10];
    const float* bg    = (const float*)d_in[11];
    const float* gamma = (const float*)d_in[12];
    const float* beta  = (const float*)d_in[13];
    float* out = (float*)d_out;

    float *pQ, *pK, *pV, *pA, *pO, *pF, *pScale, *pShift;
    cudaGetSymbolAddress((void**)&pQ, g_Q);
    cudaGetSymbolAddress((void**)&pK, g_K);
    cudaGetSymbolAddress((void**)&pV, g_V);
    cudaGetSymbolAddress((void**)&pA, g_A);
    cudaGetSymbolAddress((void**)&pO, g_O);
    cudaGetSymbolAddress((void**)&pF, g_F);
    cudaGetSymbolAddress((void**)&pScale, g_scale);
    cudaGetSymbolAddress((void**)&pShift, g_shift);

    cudaFuncSetAttribute(attn_mma, cudaFuncAttributeMaxDynamicSharedMemorySize, ATT_SMEM);

    dim3 ggrid(512, 3);
    gemm_bf16_bias<<<ggrid, 256, SMEM_BYTES>>>(wq, fs, bq, pQ, Cdim);
    gemm_bf16_bias<<<ggrid, 256, SMEM_BYTES>>>(wk, fo, bk, pK, Cdim);
    gemm_bf16_bias<<<ggrid, 256, SMEM_BYTES>>>(wv, fo, bv, pV, Cdim);

    attn_mma<<<Bb * NHh * Hh, 256, ATT_SMEM>>>(pQ, pK, pV, pA);

    gemm_bf16_bias<<<ggrid, 256, SMEM_BYTES>>>(wo, pA, bo, pO, Cdim);
    gemm_bf16_gate<<<ggrid, 256, SMEM_BYTES>>>(wg, fs, pO, bg, pF);

    bn_stats_kernel<<<Cdim, 256>>>(pF, gamma, beta, pScale, pShift);
    bn_apply_kernel<<<NELEM / 4 / 256, 256>>>(pF, pScale, pShift, out);
}

// round 17
// speedup vs baseline: 2.1347x; 1.0815x over previous
#include <cuda_runtime.h>
#include <cuda_bf16.h>
#include <math.h>
#include <cstdint>

// Problem constants
#define Cdim 384
#define NHh  4
#define HDd  96
#define Hh   64
#define Ww   128
#define Bb   8
#define HWs  8192                 // H*W
#define NELEM 25165824            // B*C*H*W
#define EPSI 1e-5f

typedef unsigned short ushortT;

// ---------------- scratch (device globals; allocation-free) ----------------
// split weights, concatenated [wq|wk|wv|wo|wg]
#define OW_Q 0
#define OW_K 147456
#define OW_V 294912
#define OW_O 442368
#define OW_G 589824
__device__ ushortT g_Wh[884736];
__device__ ushortT g_Wl[884736];
// split activations [B,C,HW] bf16
__device__ ushortT g_FSh[NELEM]; __device__ ushortT g_FSl[NELEM];
__device__ ushortT g_FOh[NELEM]; __device__ ushortT g_FOl[NELEM];
__device__ ushortT g_Qh[NELEM];  __device__ ushortT g_Ql[NELEM];
__device__ ushortT g_Kh[NELEM];  __device__ ushortT g_Kl[NELEM];
__device__ ushortT g_Vh[NELEM];  __device__ ushortT g_Vl[NELEM];
__device__ ushortT g_Ah[NELEM];  __device__ ushortT g_Al[NELEM];
__device__ ushortT g_Oh[NELEM];  __device__ ushortT g_Ol[NELEM];
__device__ float g_F[NELEM];     // fused (pre-BN), fp32
__device__ float g_scale[Cdim];
__device__ float g_shift[Cdim];

// ---------------- bf16 helpers ----------------------------------------------
__device__ __forceinline__ ushortT bfu(float x) {
    __nv_bfloat16 h = __float2bfloat16(x);
    return *reinterpret_cast<ushortT*>(&h);
}
__device__ __forceinline__ float bff(ushortT u) {
    __nv_bfloat16 h = *reinterpret_cast<__nv_bfloat16*>(&u);
    return __bfloat162float(h);
}

__device__ __forceinline__ void mma_bf16(
    float* c, uint32_t a0, uint32_t a1, uint32_t a2, uint32_t a3,
    uint32_t b0, uint32_t b1)
{
    asm volatile(
        "mma.sync.aligned.m16n8k16.row.col.f32.bf16.bf16.f32 "
        "{%0,%1,%2,%3}, {%4,%5,%6,%7}, {%8,%9}, {%0,%1,%2,%3};"
        : "+f"(c[0]), "+f"(c[1]), "+f"(c[2]), "+f"(c[3])
        : "r"(a0), "r"(a1), "r"(a2), "r"(a3), "r"(b0), "r"(b1));
}

#define LDMX4(r0, r1, r2, r3, addr) \
    asm volatile("ldmatrix.sync.aligned.m8n8.x4.shared.b16 {%0,%1,%2,%3}, [%4];" \
        : "=r"(r0), "=r"(r1), "=r"(r2), "=r"(r3) : "r"(addr))
#define LDMX4T(r0, r1, r2, r3, addr) \
    asm volatile("ldmatrix.sync.aligned.m8n8.x4.trans.shared.b16 {%0,%1,%2,%3}, [%4];" \
        : "=r"(r0), "=r"(r1), "=r"(r2), "=r"(r3) : "r"(addr))

__device__ __forceinline__ uint32_t smem_u32(const void* p) {
    uint32_t a;
    asm("{ .reg .u64 t; cvta.to.shared.u64 t, %1; cvt.u32.u64 %0, t; }" : "=r"(a) : "l"(p));
    return a;
}

#define CP16(dst, src) \
    asm volatile("cp.async.cg.shared.global [%0], [%1], 16;" :: "r"(dst), "l"(src))
#define CP_COMMIT() asm volatile("cp.async.commit_group;")
#define CP_WAIT(N)  asm volatile("cp.async.wait_group %0;" :: "n"(N))

#define SPLITPACK(ph, pl, x, y) do { \
    ushortT _hx = bfu(x), _hy = bfu(y); \
    ph = (uint32_t)_hx | ((uint32_t)_hy << 16); \
    pl = (uint32_t)bfu((x) - bff(_hx)) | ((uint32_t)bfu((y) - bff(_hy)) << 16); \
} while (0)

// stage geometry (bytes): A [128][40bf16] pitch 80; B [32][136bf16] pitch 272
#define OFF_AH 0
#define OFF_AL 10240
#define OFF_BH 20480
#define OFF_BL 29184
#define GSTAGE 37888
#define NSTAGE 4
#define GSMEM  (GSTAGE * NSTAGE)   // 151552

// ---------------- prep: split fp32 -> bf16 hi/lo ------------------------------
__global__ __launch_bounds__(256) void split_f32(
    const float* __restrict__ in, ushortT* __restrict__ hi,
    ushortT* __restrict__ lo, int n4)
{
    int i = blockIdx.x * blockDim.x + threadIdx.x;
    if (i >= n4) return;
    float4 v = ((const float4*)in)[i];
    ushortT h0 = bfu(v.x), h1 = bfu(v.y), h2 = bfu(v.z), h3 = bfu(v.w);
    ((uint2*)hi)[i] = make_uint2((uint32_t)h0 | ((uint32_t)h1 << 16),
                                 (uint32_t)h2 | ((uint32_t)h3 << 16));
    ((uint2*)lo)[i] = make_uint2(
        (uint32_t)bfu(v.x - bff(h0)) | ((uint32_t)bfu(v.y - bff(h1)) << 16),
        (uint32_t)bfu(v.z - bff(h2)) | ((uint32_t)bfu(v.w - bff(h3)) << 16));
}

// ---------------- mma on one stage -------------------------------------------
struct Acc { float a[2][8][4]; };

__device__ __forceinline__ void gemm_chunk_mma(Acc& gc, uint32_t a_lane, uint32_t b_lane)
{
#pragma unroll
    for (int ks = 0; ks < 2; ks++) {
        uint32_t ah[2][4], al[2][4];
#pragma unroll
        for (int im = 0; im < 2; im++) {
            const uint32_t aaddr = a_lane + im * 1280 + ks * 32;
            LDMX4(ah[im][0], ah[im][1], ah[im][2], ah[im][3], aaddr);
            LDMX4(al[im][0], al[im][1], al[im][2], al[im][3], aaddr + (OFF_AL - OFF_AH));
        }
#pragma unroll
        for (int jp = 0; jp < 4; jp++) {
            const uint32_t baddr = b_lane + jp * 32 + ks * 4352;
            uint32_t bh0, bh1, bh2, bh3, bl0, bl1, bl2, bl3;
            LDMX4T(bh0, bh1, bh2, bh3, baddr);
            LDMX4T(bl0, bl1, bl2, bl3, baddr + (OFF_BL - OFF_BH));
#pragma unroll
            for (int im = 0; im < 2; im++) {
                float* c0 = gc.a[im][2 * jp];
                float* c1 = gc.a[im][2 * jp + 1];
                mma_bf16(c0, ah[im][0], ah[im][1], ah[im][2], ah[im][3], bh0, bh1);
                mma_bf16(c0, ah[im][0], ah[im][1], ah[im][2], ah[im][3], bl0, bl1);
                mma_bf16(c0, al[im][0], al[im][1], al[im][2], al[im][3], bh0, bh1);
                mma_bf16(c1, ah[im][0], ah[im][1], ah[im][2], ah[im][3], bh2, bh3);
                mma_bf16(c1, ah[im][0], ah[im][1], ah[im][2], ah[im][3], bl2, bl3);
                mma_bf16(c1, al[im][0], al[im][1], al[im][2], al[im][3], bh2, bh3);
            }
        }
    }
}

// ---------------- cp.async pipelined GEMM ------------------------------------
// Out[m,t] = sum_k W[m,k] X[k,t] + b[m]; all operands pre-split bf16.
// Writes hi/lo bf16 output.
__global__ __launch_bounds__(256) void gemm_cp(
    const ushortT* __restrict__ Wh, const ushortT* __restrict__ Wl,
    const ushortT* __restrict__ Xh, const ushortT* __restrict__ Xl,
    const float* __restrict__ bias,
    ushortT* __restrict__ Oh, ushortT* __restrict__ Ol, int Kdim)
{
    extern __shared__ char smb[];
    const int tid = threadIdx.x;
    const int wid = tid >> 5, lane = tid & 31;
    const int g = lane >> 2, tg = lane & 3;
    const int bIdx = blockIdx.x >> 6;
    const int s0   = (blockIdx.x & 63) << 7;
    const int m0   = blockIdx.y << 7;
    const int wm = (wid & 3) << 5;
    const int wt = (wid >> 2) << 6;

    const ushortT* Xbh = Xh + (size_t)bIdx * Kdim * HWs + s0;
    const ushortT* Xbl = Xl + (size_t)bIdx * Kdim * HWs + s0;

    Acc gc;
#pragma unroll
    for (int im = 0; im < 2; im++)
#pragma unroll
        for (int jf = 0; jf < 8; jf++)
#pragma unroll
            for (int e = 0; e < 4; e++) gc.a[im][jf][e] = 0.f;

    const uint32_t smu = smem_u32(smb);
    const uint32_t a_lane = smu + OFF_AH + (wm + (lane & 15)) * 80 + (lane >> 4) * 16;
    const uint32_t b_lane = smu + OFF_BH + (lane & 15) * 272 + (lane >> 4) * 16 + wt * 2;

    const int nchunk = Kdim >> 5;

#define G_ISSUE(ic) do { \
    const uint32_t sb = smu + (uint32_t)(((ic) & 3) * GSTAGE); \
    const int k0 = (ic) << 5; \
    _Pragma("unroll") \
    for (int u = 0; u < 2; u++) { \
        const int ci = (tid << 1) + u; \
        const int ar = ci >> 2, ac = ci & 3; \
        const size_t wo_ = (size_t)(m0 + ar) * Kdim + k0 + ac * 8; \
        CP16(sb + OFF_AH + ar * 80 + ac * 16, Wh + wo_); \
        CP16(sb + OFF_AL + ar * 80 + ac * 16, Wl + wo_); \
        const int br = ci >> 4, bc = ci & 15; \
        const size_t xo_ = (size_t)(k0 + br) * HWs + bc * 8; \
        CP16(sb + OFF_BH + br * 272 + bc * 16, Xbh + xo_); \
        CP16(sb + OFF_BL + br * 272 + bc * 16, Xbl + xo_); \
    } \
} while (0)

    G_ISSUE(0); CP_COMMIT();
    G_ISSUE(1); CP_COMMIT();
    G_ISSUE(2); CP_COMMIT();

    for (int ic = 0; ic < nchunk; ic++) {
        if (ic + 3 < nchunk) { G_ISSUE(ic + 3); CP_COMMIT(); CP_WAIT(3); }
        else                 { CP_WAIT(0); }
        __syncthreads();
        const uint32_t so = (uint32_t)((ic & 3) * GSTAGE);
        gemm_chunk_mma(gc, a_lane + so, b_lane + so);
        __syncthreads();
    }
#undef G_ISSUE

    ushortT* Obh = Oh + (size_t)bIdx * Cdim * HWs + s0;
    ushortT* Obl = Ol + (size_t)bIdx * Cdim * HWs + s0;
#pragma unroll
    for (int im = 0; im < 2; im++) {
        const int m1 = m0 + wm + (im << 4) + g;
        const float bv1 = bias[m1], bv2 = bias[m1 + 8];
        const size_t r1 = (size_t)m1 * HWs, r2 = r1 + (size_t)8 * HWs;
#pragma unroll
        for (int jf = 0; jf < 8; jf++) {
            const int tl = wt + (jf << 3) + (tg << 1);
            const float* c = gc.a[im][jf];
            uint32_t h, l;
            SPLITPACK(h, l, c[0] + bv1, c[1] + bv1);
            *(uint32_t*)(Obh + r1 + tl) = h;
            *(uint32_t*)(Obl + r1 + tl) = l;
            SPLITPACK(h, l, c[2] + bv2, c[3] + bv2);
            *(uint32_t*)(Obh + r2 + tl) = h;
            *(uint32_t*)(Obl + r2 + tl) = l;
        }
    }
}

// ---------------- gate GEMM (K=768 concat) + fused sigmoid epilogue ----------
__global__ __launch_bounds__(256) void gemm_cp_gate(
    const ushortT* __restrict__ Wh, const ushortT* __restrict__ Wl,
    const ushortT* __restrict__ FSh, const ushortT* __restrict__ FSl,
    const ushortT* __restrict__ OPh, const ushortT* __restrict__ OPl,
    const float* __restrict__ FS32, const float* __restrict__ bias,
    float* __restrict__ Fused)
{
    extern __shared__ char smb[];
    const int tid = threadIdx.x;
    const int wid = tid >> 5, lane = tid & 31;
    const int g = lane >> 2, tg = lane & 3;
    const int bIdx = blockIdx.x >> 6;
    const int s0   = (blockIdx.x & 63) << 7;
    const int m0   = blockIdx.y << 7;
    const int wm = (wid & 3) << 5;
    const int wt = (wid >> 2) << 6;

    const size_t actb = (size_t)bIdx * Cdim * HWs + s0;
    const ushortT* FSbh = FSh + actb;
    const ushortT* FSbl = FSl + actb;
    const ushortT* OPbh = OPh + actb;
    const ushortT* OPbl = OPl + actb;

    Acc gc;
#pragma unroll
    for (int im = 0; im < 2; im++)
#pragma unroll
        for (int jf = 0; jf < 8; jf++)
#pragma unroll
            for (int e = 0; e < 4; e++) gc.a[im][jf][e] = 0.f;

    const uint32_t smu = smem_u32(smb);
    const uint32_t a_lane = smu + OFF_AH + (wm + (lane & 15)) * 80 + (lane >> 4) * 16;
    const uint32_t b_lane = smu + OFF_BH + (lane & 15) * 272 + (lane >> 4) * 16 + wt * 2;

#define GG_ISSUE(ic) do { \
    const uint32_t sb = smu + (uint32_t)(((ic) & 3) * GSTAGE); \
    const int k0 = (ic) << 5; \
    _Pragma("unroll") \
    for (int u = 0; u < 2; u++) { \
        const int ci = (tid << 1) + u; \
        const int ar = ci >> 2, ac = ci & 3; \
        const size_t wo_ = (size_t)(m0 + ar) * 768 + k0 + ac * 8; \
        CP16(sb + OFF_AH + ar * 80 + ac * 16, Wh + wo_); \
        CP16(sb + OFF_AL + ar * 80 + ac * 16, Wl + wo_); \
        const int br = ci >> 4, bc = ci & 15; \
        const int kg = k0 + br; \
        const ushortT* rh = (kg < Cdim) ? (FSbh + (size_t)kg * HWs) \
                                        : (OPbh + (size_t)(kg - Cdim) * HWs); \
        const ushortT* rl = (kg < Cdim) ? (FSbl + (size_t)kg * HWs) \
                                        : (OPbl + (size_t)(kg - Cdim) * HWs); \
        CP16(sb + OFF_BH + br * 272 + bc * 16, rh + bc * 8); \
        CP16(sb + OFF_BL + br * 272 + bc * 16, rl + bc * 8); \
    } \
} while (0)

    GG_ISSUE(0); CP_COMMIT();
    GG_ISSUE(1); CP_COMMIT();
    GG_ISSUE(2); CP_COMMIT();

    for (int ic = 0; ic < 24; ic++) {
        if (ic + 3 < 24) { GG_ISSUE(ic + 3); CP_COMMIT(); CP_WAIT(3); }
        else             { CP_WAIT(0); }
        __syncthreads();
        const uint32_t so = (uint32_t)((ic & 3) * GSTAGE);
        gemm_chunk_mma(gc, a_lane + so, b_lane + so);
        __syncthreads();
    }
#undef GG_ISSUE

    const float* FSb = FS32 + actb;
    float* Fb = Fused + actb;
#pragma unroll
    for (int im = 0; im < 2; im++) {
        const int m1 = m0 + wm + (im << 4) + g;
        const float bv1 = bias[m1], bv2 = bias[m1 + 8];
        const size_t r1 = (size_t)m1 * HWs, r2 = r1 + (size_t)8 * HWs;
#pragma unroll
        for (int jf = 0; jf < 8; jf++) {
            const int tl = wt + (jf << 3) + (tg << 1);
            const float* c = gc.a[im][jf];
            float2 f1 = *(const float2*)(FSb + r1 + tl);
            float2 f2 = *(const float2*)(FSb + r2 + tl);
            uint32_t p1h = *(const uint32_t*)(OPbh + r1 + tl);
            uint32_t p1l = *(const uint32_t*)(OPbl + r1 + tl);
            uint32_t p2h = *(const uint32_t*)(OPbh + r2 + tl);
            uint32_t p2l = *(const uint32_t*)(OPbl + r2 + tl);
            float o10 = bff((ushortT)p1h) + bff((ushortT)p1l);
            float o11 = bff((ushortT)(p1h >> 16)) + bff((ushortT)(p1l >> 16));
            float o20 = bff((ushortT)p2h) + bff((ushortT)p2l);
            float o21 = bff((ushortT)(p2h >> 16)) + bff((ushortT)(p2l >> 16));
            float g0 = 1.f / (1.f + __expf(-(c[0] + bv1)));
            float g1 = 1.f / (1.f + __expf(-(c[1] + bv1)));
            float g2 = 1.f / (1.f + __expf(-(c[2] + bv2)));
            float g3 = 1.f / (1.f + __expf(-(c[3] + bv2)));
            *(float2*)(Fb + r1 + tl) = make_float2(f1.x + g0 * o10, f1.y + g1 * o11);
            *(float2*)(Fb + r2 + tl) = make_float2(f2.x + g2 * o20, f2.y + g3 * o21);
        }
    }
}

// ---------------- tensor-core epipolar attention (bf16-pair IO) ---------------
#define AQH 0
#define AQL 26112
#define AKH 52224
#define AKL 78336
#define AVH 104448
#define AVL 130560
#define ATT_SMEM 156672

__global__ __launch_bounds__(256, 1) void attn_mma(
    const ushortT* __restrict__ Qh, const ushortT* __restrict__ Ql,
    const ushortT* __restrict__ Kh, const ushortT* __restrict__ Kl,
    const ushortT* __restrict__ Vh, const ushortT* __restrict__ Vl,
    ushortT* __restrict__ Ah, ushortT* __restrict__ Al)
{
    extern __shared__ char smb[];
    const uint32_t smu = smem_u32(smb);

    const int gblk = blockIdx.x;
    const int h = gblk & 63;
    const int n = (gblk >> 6) & 3;
    const int b = gblk >> 8;
    const size_t base = ((size_t)b * Cdim + (size_t)n * HDd) * HWs + (size_t)h * Ww;

    const int tid = threadIdx.x;
    const int wid = tid >> 5, lane = tid & 31;
    const int g = lane >> 2, tg = lane & 3;
    const int wm = wid << 4;

    const float sc = 0.10206207261596575f;   // 1/sqrt(96)

    // ---- cp.async copy of 6 bf16 arrays into smem ----
    for (int i = tid; i < 1536; i += 256) {
        const int row = i >> 4, c16 = i & 15;
        const uint32_t so = (uint32_t)row * 272 + (uint32_t)c16 * 16;
        const size_t go = base + (size_t)row * HWs + c16 * 8;
        CP16(smu + AQH + so, Qh + go); CP16(smu + AQL + so, Ql + go);
        CP16(smu + AKH + so, Kh + go); CP16(smu + AKL + so, Kl + go);
        CP16(smu + AVH + so, Vh + go); CP16(smu + AVL + so, Vl + go);
    }
    CP_COMMIT(); CP_WAIT(0);
    __syncthreads();

    // ---- S = Q K^T ----
    const uint32_t qaddr = smu + AQH
        + (uint32_t)((lane & 7) + ((lane >> 4) << 3)) * 272
        + (uint32_t)(wm + (((lane >> 3) & 1) << 3)) * 2;
    const uint32_t kaddr = smu + AKH
        + (uint32_t)(lane & 15) * 272 + (uint32_t)((lane >> 4) << 4);

    float sacc[16][4];
#pragma unroll
    for (int jf = 0; jf < 16; jf++)
#pragma unroll
        for (int e = 0; e < 4; e++) sacc[jf][e] = 0.f;

#pragma unroll
    for (int kc = 0; kc < 6; kc++) {
        uint32_t qh[4], ql[4];
        LDMX4T(qh[0], qh[1], qh[2], qh[3], qaddr + kc * 4352);
        LDMX4T(ql[0], ql[1], ql[2], ql[3], qaddr + kc * 4352 + (AQL - AQH));
#pragma unroll
        for (int jp = 0; jp < 8; jp++) {
            uint32_t kh0, kh1, kh2, kh3, kl0, kl1, kl2, kl3;
            const uint32_t ka = kaddr + kc * 4352 + jp * 32;
            LDMX4T(kh0, kh1, kh2, kh3, ka);
            LDMX4T(kl0, kl1, kl2, kl3, ka + (AKL - AKH));
            float* c0 = sacc[2 * jp];
            float* c1 = sacc[2 * jp + 1];
            mma_bf16(c0, qh[0], qh[1], qh[2], qh[3], kh0, kh1);
            mma_bf16(c0, qh[0], qh[1], qh[2], qh[3], kl0, kl1);
            mma_bf16(c0, ql[0], ql[1], ql[2], ql[3], kh0, kh1);
            mma_bf16(c1, qh[0], qh[1], qh[2], qh[3], kh2, kh3);
            mma_bf16(c1, qh[0], qh[1], qh[2], qh[3], kl2, kl3);
            mma_bf16(c1, ql[0], ql[1], ql[2], ql[3], kh2, kh3);
        }
    }
    __syncthreads();

    // ---- scale + softmax in registers ----
#pragma unroll
    for (int jf = 0; jf < 16; jf++) {
        sacc[jf][0] *= sc; sacc[jf][1] *= sc;
        sacc[jf][2] *= sc; sacc[jf][3] *= sc;
    }
    float m0 = -1e30f, m1 = -1e30f;
#pragma unroll
    for (int jf = 0; jf < 16; jf++) {
        m0 = fmaxf(m0, fmaxf(sacc[jf][0], sacc[jf][1]));
        m1 = fmaxf(m1, fmaxf(sacc[jf][2], sacc[jf][3]));
    }
    m0 = fmaxf(m0, __shfl_xor_sync(0xffffffffu, m0, 1));
    m0 = fmaxf(m0, __shfl_xor_sync(0xffffffffu, m0, 2));
    m1 = fmaxf(m1, __shfl_xor_sync(0xffffffffu, m1, 1));
    m1 = fmaxf(m1, __shfl_xor_sync(0xffffffffu, m1, 2));
    float s0 = 0.f, s1 = 0.f;
#pragma unroll
    for (int jf = 0; jf < 16; jf++) {
        float e0 = __expf(sacc[jf][0] - m0);
        float e1 = __expf(sacc[jf][1] - m0);
        float e2 = __expf(sacc[jf][2] - m1);
        float e3 = __expf(sacc[jf][3] - m1);
        sacc[jf][0] = e0; sacc[jf][1] = e1; sacc[jf][2] = e2; sacc[jf][3] = e3;
        s0 += e0 + e1; s1 += e2 + e3;
    }
    s0 += __shfl_xor_sync(0xffffffffu, s0, 1);
    s0 += __shfl_xor_sync(0xffffffffu, s0, 2);
    s1 += __shfl_xor_sync(0xffffffffu, s1, 1);
    s1 += __shfl_xor_sync(0xffffffffu, s1, 2);
    const float i0 = 1.f / s0, i1 = 1.f / s1;
#pragma unroll
    for (int jf = 0; jf < 16; jf++) {
        sacc[jf][0] *= i0; sacc[jf][1] *= i0;
        sacc[jf][2] *= i1; sacc[jf][3] *= i1;
    }

    // ---- O = P V ----
    const uint32_t vaddr = smu + AVH
        + (uint32_t)((lane & 7) + ((lane >> 4) << 3)) * 272
        + (uint32_t)(((lane >> 3) & 1) << 4);

    float oacc[12][4];
#pragma unroll
    for (int jt = 0; jt < 12; jt++)
#pragma unroll
        for (int e = 0; e < 4; e++) oacc[jt][e] = 0.f;

#pragma unroll
    for (int kc = 0; kc < 8; kc++) {
        uint32_t ph[4], pl[4];
        SPLITPACK(ph[0], pl[0], sacc[2 * kc][0], sacc[2 * kc][1]);
        SPLITPACK(ph[1], pl[1], sacc[2 * kc][2], sacc[2 * kc][3]);
        SPLITPACK(ph[2], pl[2], sacc[2 * kc + 1][0], sacc[2 * kc + 1][1]);
        SPLITPACK(ph[3], pl[3], sacc[2 * kc + 1][2], sacc[2 * kc + 1][3]);
#pragma unroll
        for (int jc = 0; jc < 6; jc++) {
            uint32_t vh0, vh1, vh2, vh3, vl0, vl1, vl2, vl3;
            const uint32_t va = vaddr + jc * 4352 + kc * 32;
            LDMX4(vh0, vh1, vh2, vh3, va);
            LDMX4(vl0, vl1, vl2, vl3, va + (AVL - AVH));
            float* d0 = oacc[2 * jc];
            float* d1 = oacc[2 * jc + 1];
            mma_bf16(d0, ph[0], ph[1], ph[2], ph[3], vh0, vh1);
            mma_bf16(d0, ph[0], ph[1], ph[2], ph[3], vl0, vl1);
            mma_bf16(d0, pl[0], pl[1], pl[2], pl[3], vh0, vh1);
            mma_bf16(d1, ph[0], ph[1], ph[2], ph[3], vh2, vh3);
            mma_bf16(d1, ph[0], ph[1], ph[2], ph[3], vl2, vl3);
            mma_bf16(d1, pl[0], pl[1], pl[2], pl[3], vh2, vh3);
        }
    }

    // ---- stage O[c][w] fp32 in smem, then split-store to Ah/Al ----
    float* Osm = (float*)smb;
#pragma unroll
    for (int jt = 0; jt < 12; jt++) {
        const int c = (jt << 3) + (tg << 1);
        const int w = wm + g;
        Osm[c * 132 + w]            = oacc[jt][0];
        Osm[(c + 1) * 132 + w]      = oacc[jt][1];
        Osm[c * 132 + w + 8]        = oacc[jt][2];
        Osm[(c + 1) * 132 + w + 8]  = oacc[jt][3];
    }
    __syncthreads();

    for (int i = tid; i < 96 * 32; i += 256) {
        const int c = i >> 5, w4 = (i & 31) << 2;
        const float4 v = *(const float4*)(Osm + c * 132 + w4);
        ushortT h0 = bfu(v.x), h1 = bfu(v.y), h2 = bfu(v.z), h3 = bfu(v.w);
        uint2 hv = make_uint2((uint32_t)h0 | ((uint32_t)h1 << 16),
                              (uint32_t)h2 | ((uint32_t)h3 << 16));
        uint2 lv = make_uint2(
            (uint32_t)bfu(v.x - bff(h0)) | ((uint32_t)bfu(v.y - bff(h1)) << 16),
            (uint32_t)bfu(v.z - bff(h2)) | ((uint32_t)bfu(v.w - bff(h3)) << 16));
        const size_t go = base + (size_t)c * HWs + w4;
        *(uint2*)(Ah + go) = hv;
        *(uint2*)(Al + go) = lv;
    }
}

// ---------------- BatchNorm: stats then apply (proven) ------------------------
__global__ __launch_bounds__(256) void bn_stats_kernel(
    const float* __restrict__ F, const float* __restrict__ gamma,
    const float* __restrict__ beta, float* __restrict__ scale,
    float* __restrict__ shift)
{
    const int c = blockIdx.x;
    const int tid = threadIdx.x;
    float s = 0.f, s2 = 0.f;
    for (int i = tid; i < Bb * HWs; i += 256) {
        int b = i >> 13, sp = i & 8191;
        float v = F[(size_t)b * Cdim * HWs + (size_t)c * HWs + sp];
        s += v; s2 += v * v;
    }
    __shared__ float rs[256], rs2[256];
    rs[tid] = s; rs2[tid] = s2;
    __syncthreads();
    for (int o = 128; o > 0; o >>= 1) {
        if (tid < o) { rs[tid] += rs[tid + o]; rs2[tid] += rs2[tid + o]; }
        __syncthreads();
    }
    if (tid == 0) {
        float mean = rs[0] * (1.f / 65536.f);
        float var  = rs2[0] * (1.f / 65536.f) - mean * mean;
        float sv = gamma[c] * rsqrtf(var + EPSI);
        scale[c] = sv;
        shift[c] = beta[c] - mean * sv;
    }
}

__global__ __launch_bounds__(256) void bn_apply_kernel(
    const float* __restrict__ F, const float* __restrict__ scale,
    const float* __restrict__ shift, float* __restrict__ Out)
{
    int idx = blockIdx.x * blockDim.x + threadIdx.x;
    if (idx >= NELEM / 4) return;
    int c = (idx >> 11) % Cdim;
    float sv = scale[c], sh = shift[c];
    float4 v = ((const float4*)F)[idx];
    float4 o = make_float4(v.x * sv + sh, v.y * sv + sh, v.z * sv + sh, v.w * sv + sh);
    ((float4*)Out)[idx] = o;
}

// ---------------- launch ------------------------------------------------------
extern "C" void kernel_launch(void* const* d_in, const int* in_sizes, int n_in,
                              void* d_out, int out_size)
{
    const float* fs    = (const float*)d_in[0];
    const float* fo    = (const float*)d_in[1];
    const float* wq    = (const float*)d_in[2];
    const float* bq    = (const float*)d_in[3];
    const float* wk    = (const float*)d_in[4];
    const float* bk    = (const float*)d_in[5];
    const float* wv    = (const float*)d_in[6];
    const float* bv    = (const float*)d_in[7];
    const float* wo    = (const float*)d_in[8];
    const float* bo    = (const float*)d_in[9];
    const float* wg    = (const float*)d_in[10];
    const float* bg    = (const float*)d_in[11];
    const float* gamma = (const float*)d_in[12];
    const float* beta  = (const float*)d_in[13];
    float* out = (float*)d_out;

    ushortT *pWh, *pWl, *pFSh, *pFSl, *pFOh, *pFOl;
    ushortT *pQh, *pQl, *pKh, *pKl, *pVh, *pVl, *pAh, *pAl, *pOh, *pOl;
    float *pF, *pScale, *pShift;
    cudaGetSymbolAddress((void**)&pWh, g_Wh);
    cudaGetSymbolAddress((void**)&pWl, g_Wl);
    cudaGetSymbolAddress((void**)&pFSh, g_FSh);
    cudaGetSymbolAddress((void**)&pFSl, g_FSl);
    cudaGetSymbolAddress((void**)&pFOh, g_FOh);
    cudaGetSymbolAddress((void**)&pFOl, g_FOl);
    cudaGetSymbolAddress((void**)&pQh, g_Qh);
    cudaGetSymbolAddress((void**)&pQl, g_Ql);
    cudaGetSymbolAddress((void**)&pKh, g_Kh);
    cudaGetSymbolAddress((void**)&pKl, g_Kl);
    cudaGetSymbolAddress((void**)&pVh, g_Vh);
    cudaGetSymbolAddress((void**)&pVl, g_Vl);
    cudaGetSymbolAddress((void**)&pAh, g_Ah);
    cudaGetSymbolAddress((void**)&pAl, g_Al);
    cudaGetSymbolAddress((void**)&pOh, g_Oh);
    cudaGetSymbolAddress((void**)&pOl, g_Ol);
    cudaGetSymbolAddress((void**)&pF, g_F);
    cudaGetSymbolAddress((void**)&pScale, g_scale);
    cudaGetSymbolAddress((void**)&pShift, g_shift);

    cudaFuncSetAttribute(gemm_cp, cudaFuncAttributeMaxDynamicSharedMemorySize, GSMEM);
    cudaFuncSetAttribute(gemm_cp_gate, cudaFuncAttributeMaxDynamicSharedMemorySize, GSMEM);
    cudaFuncSetAttribute(attn_mma, cudaFuncAttributeMaxDynamicSharedMemorySize, ATT_SMEM);

    // prep: split weights + input activations
    split_f32<<<144, 256>>>(wq, pWh + OW_Q, pWl + OW_Q, 36864);
    split_f32<<<144, 256>>>(wk, pWh + OW_K, pWl + OW_K, 36864);
    split_f32<<<144, 256>>>(wv, pWh + OW_V, pWl + OW_V, 36864);
    split_f32<<<144, 256>>>(wo, pWh + OW_O, pWl + OW_O, 36864);
    split_f32<<<288, 256>>>(wg, pWh + OW_G, pWl + OW_G, 73728);
    split_f32<<<24576, 256>>>(fs, pFSh, pFSl, NELEM / 4);
    split_f32<<<24576, 256>>>(fo, pFOh, pFOl, NELEM / 4);

    dim3 ggrid(512, 3);
    gemm_cp<<<ggrid, 256, GSMEM>>>(pWh + OW_Q, pWl + OW_Q, pFSh, pFSl, bq, pQh, pQl, 384);
    gemm_cp<<<ggrid, 256, GSMEM>>>(pWh + OW_K, pWl + OW_K, pFOh, pFOl, bk, pKh, pKl, 384);
    gemm_cp<<<ggrid, 256, GSMEM>>>(pWh + OW_V, pWl + OW_V, pFOh, pFOl, bv, pVh, pVl, 384);

    attn_mma<<<Bb * NHh * Hh, 256, ATT_SMEM>>>(pQh, pQl, pKh, pKl, pVh, pVl, pAh, pAl);

    gemm_cp<<<ggrid, 256, GSMEM>>>(pWh + OW_O, pWl + OW_O, pAh, pAl, bo, pOh, pOl, 384);
    gemm_cp_gate<<<ggrid, 256, GSMEM>>>(pWh + OW_G, pWl + OW_G, pFSh, pFSl, pOh, pOl,
                                        fs, bg, pF);

    bn_stats_kernel<<<Cdim, 256>>>(pF, gamma, beta, pScale, pShift);
    bn_apply_kernel<<<NELEM / 4 / 256, 256>>>(pF, pScale, pShift, out);
}